// round 6
// baseline (speedup 1.0000x reference)
#include <cuda_runtime.h>
#include <cuda_fp16.h>
#include <cstdint>

// ============================================================================
// VectorQuantizerEMA — persistent-CTA HMMA (m16n8k16 fp16, single pass) with
// exact-margin fp32 recheck. sm_100-safe PTX only.
// ============================================================================

#define NC      512
#define CD      64
#define NROWS   (64 * 4096)
#define NELEM   (NROWS * CD)
#define NTILES  2048
#define GRID    148
#define TAU     0.25f

#define O_ZQ    ((size_t)0)
#define O_LOSS  ((size_t)16777216)
#define O_IDX   ((size_t)16777217)
#define O_NEMB  ((size_t)17039361)
#define O_NCS   ((size_t)17072129)
#define O_NAVG  ((size_t)17072641)

// ---- device scratch --------------------------------------------------------
__device__ __align__(16) float g_esum[NC * CD];
__device__ __align__(16) unsigned short g_Bh16[NC * CD];  // fp16 E, row-major
__device__ float g_counts[NC];
__device__ float g_h[NC];            // 0.5*||e||^2
__device__ float g_sse;

// ---- smem layout (bytes) ---------------------------------------------------
#define SM_Z0    0        // 32KB raw z tile (double buffer A)
#define SM_Z1    32768    // 32KB raw z tile (double buffer B)
#define SM_AH    65536    // 16KB fp16 A, swizzled for ldmatrix
#define SM_E     81920    // 64KB fp32 E half (recheck staging)
#define SM_R2    147456   // 16KB float2 (best, best2) per (row, warp)
#define SM_RI    163840   // 4KB  u16 best-idx per (row, warp)
#define SM_H     167936   // 2KB
#define SM_CNT   169984   // 2KB
#define SM_BI    172032   // 512B
#define SM_LIST  172544   // 512B
#define SM_NFLG  173056
#define SMEM_SZ  173312

__device__ __forceinline__ uint32_t smem_u32(const void* p) {
    uint32_t a;
    asm("{ .reg .u64 t; cvta.to.shared.u64 t, %1; cvt.u32.u64 %0, t; }" : "=r"(a) : "l"(p));
    return a;
}
__device__ __forceinline__ void ldsm_x4(uint32_t a, uint32_t* r) {
    asm volatile("ldmatrix.sync.aligned.m8n8.x4.shared.b16 {%0,%1,%2,%3}, [%4];"
        : "=r"(r[0]), "=r"(r[1]), "=r"(r[2]), "=r"(r[3]) : "r"(a));
}
__device__ __forceinline__ void mma16816(float* c, const uint32_t* a, const uint32_t* b) {
    asm volatile("mma.sync.aligned.m16n8k16.row.col.f32.f16.f16.f32 "
        "{%0,%1,%2,%3}, {%4,%5,%6,%7}, {%8,%9}, {%0,%1,%2,%3};"
        : "+f"(c[0]), "+f"(c[1]), "+f"(c[2]), "+f"(c[3])
        : "r"(a[0]), "r"(a[1]), "r"(a[2]), "r"(a[3]), "r"(b[0]), "r"(b[1]));
}
__device__ __forceinline__ uint32_t packh(float x, float y) {
    __half2 h = __floats2half2_rn(x, y);
    return *(uint32_t*)&h;
}
__device__ __forceinline__ void cp16(uint32_t d, const void* s) {
    asm volatile("cp.async.cg.shared.global [%0], [%1], 16;" :: "r"(d), "l"(s));
}
#define CP_COMMIT() asm volatile("cp.async.commit_group;")
#define CP_WAIT0()  asm volatile("cp.async.wait_group 0;")

// ============================================================================
// Kernel 1: zero scratch, half-norms, fp16 B
// ============================================================================
__global__ void vq_init(const float* __restrict__ emb) {
    int t = blockIdx.x * blockDim.x + threadIdx.x;   // 64 x 512 = 32768
    if (t < NC * CD) {
        g_esum[t] = 0.0f;
        g_Bh16[t] = __half_as_ushort(__float2half_rn(emb[t]));
    }
    if (t == 0) g_sse = 0.0f;
    if (t < NC) {
        g_counts[t] = 0.0f;
        const float4* e = (const float4*)(emb + (size_t)t * CD);
        float s = 0.0f;
#pragma unroll
        for (int i = 0; i < CD / 4; i++) {
            float4 v = e[i];
            s += v.x * v.x + v.y * v.y + v.z * v.z + v.w * v.w;
        }
        g_h[t] = 0.5f * s;
    }
}

// no-op spacers so ncu -s 5 lands on vq_main
__global__ void vq_nop1() {}
__global__ void vq_nop2() {}

// ============================================================================
// Kernel 2: persistent main. 148 CTAs x 512 thr (16 warps), ~14 tiles each.
// Warp w owns codes [32w, 32w+32); B fragments register-resident for the
// whole kernel (loaded straight from gmem; m16n8k16 B frag = contiguous
// fp16 pairs of E rows). z tiles prefetched via cp.async double buffer.
// ============================================================================
__global__ void __launch_bounds__(512, 1)
vq_main(const float* __restrict__ z, const float* __restrict__ emb,
        float* __restrict__ out) {
    extern __shared__ __align__(16) char smem[];
    const uint32_t sb32 = smem_u32(smem);
    float*  sH   = (float*)(smem + SM_H);
    float*  sCnt = (float*)(smem + SM_CNT);
    int*    sBI  = (int*)(smem + SM_BI);
    int*    sLst = (int*)(smem + SM_LIST);
    int*    sNF  = (int*)(smem + SM_NFLG);
    float2* sR2  = (float2*)(smem + SM_R2);
    unsigned short* sRI = (unsigned short*)(smem + SM_RI);

    const int tid  = threadIdx.x;
    const int wid  = tid >> 5;
    const int lane = tid & 31;

    // ---- prologue: prefetch first tile, stage h, zero counters ----
    {
        uint32_t dst = sb32 + SM_Z0;
        const char* src = (const char*)(z + (size_t)blockIdx.x * 128 * CD);
#pragma unroll
        for (int i = 0; i < 4; i++) {
            int c = tid + i * 512;
            cp16(dst + c * 16, src + c * 16);
        }
        CP_COMMIT();
    }
    sH[tid] = g_h[tid];
    sCnt[tid] = 0.0f;
    __syncthreads();

    const int jw = wid * 32;
    // ---- hoist B fragments (once per kernel): 4 nt x 4 ks x {b0,b1} ----
    uint32_t Breg[4][4][2];
#pragma unroll
    for (int nt = 0; nt < 4; nt++) {
        int code = jw + nt * 8 + (lane >> 2);
        const uint32_t* row = (const uint32_t*)(g_Bh16 + (size_t)code * CD);
#pragma unroll
        for (int ks = 0; ks < 4; ks++) {
            int k2 = ks * 8 + (lane & 3);
            Breg[nt][ks][0] = row[k2];
            Breg[nt][ks][1] = row[k2 + 4];
        }
    }
    float hreg[8];
#pragma unroll
    for (int nt = 0; nt < 4; nt++) {
        hreg[nt * 2]     = sH[jw + nt * 8 + 2 * (lane & 3)];
        hreg[nt * 2 + 1] = sH[jw + nt * 8 + 2 * (lane & 3) + 1];
    }

    float sse_acc = 0.0f;
    int it = 0;
#pragma unroll 1
    for (int tile = blockIdx.x; tile < NTILES; tile += GRID, it++) {
        const uint32_t zoff = (it & 1) ? SM_Z1 : SM_Z0;

        CP_WAIT0();
        __syncthreads();                 // z tile resident; prev epilogue done

        // ---- convert: raw z (smem) -> fp16 AH (swizzled) ----
        {
            int row = tid >> 2, q = tid & 3;
            const float4* zr = (const float4*)(smem + zoff + row * 256 + q * 64);
            float4 v0 = zr[0], v1 = zr[1], v2 = zr[2], v3 = zr[3];
            uint4 H0, H1;
            H0.x = packh(v0.x, v0.y); H0.y = packh(v0.z, v0.w);
            H0.z = packh(v1.x, v1.y); H0.w = packh(v1.z, v1.w);
            H1.x = packh(v2.x, v2.y); H1.y = packh(v2.z, v2.w);
            H1.z = packh(v3.x, v3.y); H1.w = packh(v3.z, v3.w);
            uint4* pH = (uint4*)(smem + SM_AH + row * 128);
            pH[(2 * q) ^ (row & 7)]     = H0;
            pH[(2 * q + 1) ^ (row & 7)] = H1;
        }
        if (tid == 0) *sNF = 0;

        // ---- prefetch next tile into other buffer (overlaps MMA) ----
        {
            int tn = tile + GRID;
            if (tn < NTILES) {
                uint32_t dst = sb32 + ((it & 1) ? SM_Z0 : SM_Z1);
                const char* src = (const char*)(z + (size_t)tn * 128 * CD);
#pragma unroll
                for (int i = 0; i < 4; i++) {
                    int c = tid + i * 512;
                    cp16(dst + c * 16, src + c * 16);
                }
            }
            CP_COMMIT();
        }
        __syncthreads();                 // AH visible to all warps

        // ---- MMA mainloop: 8 row-tiles of m16n8k16 ----
#pragma unroll 1
        for (int rt = 0; rt < 8; rt++) {
            uint32_t Ah[16];
            {
                int rl = 16 * rt + (lane & 7) + (((lane >> 3) & 1) << 3);
                int ch = (lane >> 4) & 1;
                uint32_t baseH = sb32 + SM_AH + rl * 128;
                int sw = rl & 7;
#pragma unroll
                for (int ks = 0; ks < 4; ks++)
                    ldsm_x4(baseH + (((2 * ks + ch) ^ sw) << 4), &Ah[ks * 4]);
            }
            float C[16];
#pragma unroll
            for (int i = 0; i < 16; i++) C[i] = 0.0f;
#pragma unroll
            for (int nt = 0; nt < 4; nt++)
#pragma unroll
                for (int ks = 0; ks < 4; ks++)
                    mma16816(&C[nt * 4], &Ah[ks * 4], Breg[nt][ks]);

            // ---- extraction: rows g=lane/4 and g+8 ----
            float b1a = -3.4e38f, b2a = -3.4e38f; int i1a = 0;
            float b1b = -3.4e38f, b2b = -3.4e38f; int i1b = 0;
#pragma unroll
            for (int nt = 0; nt < 4; nt++) {
#pragma unroll
                for (int u = 0; u < 2; u++) {
                    int j = jw + nt * 8 + 2 * (lane & 3) + u;
                    float s = C[nt * 4 + u] - hreg[nt * 2 + u];
                    if (s > b1a) { b2a = b1a; b1a = s; i1a = j; }
                    else if (s > b2a) b2a = s;
                    float s2 = C[nt * 4 + 2 + u] - hreg[nt * 2 + u];
                    if (s2 > b1b) { b2b = b1b; b1b = s2; i1b = j; }
                    else if (s2 > b2b) b2b = s2;
                }
            }
#pragma unroll
            for (int m = 1; m <= 2; m <<= 1) {
                float ob  = __shfl_xor_sync(0xffffffffu, b1a, m);
                float ob2 = __shfl_xor_sync(0xffffffffu, b2a, m);
                int   oi  = __shfl_xor_sync(0xffffffffu, i1a, m);
                bool take = (ob > b1a) || (ob == b1a && oi < i1a);
                float loser = take ? b1a : ob;
                b2a = fmaxf(fmaxf(b2a, ob2), loser);
                if (take) { b1a = ob; i1a = oi; }
                ob  = __shfl_xor_sync(0xffffffffu, b1b, m);
                ob2 = __shfl_xor_sync(0xffffffffu, b2b, m);
                oi  = __shfl_xor_sync(0xffffffffu, i1b, m);
                take = (ob > b1b) || (ob == b1b && oi < i1b);
                loser = take ? b1b : ob;
                b2b = fmaxf(fmaxf(b2b, ob2), loser);
                if (take) { b1b = ob; i1b = oi; }
            }
            if ((lane & 3) == 0) {
                int g = lane >> 2;
                int r0 = 16 * rt + g, r1 = r0 + 8;
                sR2[r0 * 16 + wid] = make_float2(b1a, b2a);
                sRI[r0 * 16 + wid] = (unsigned short)i1a;
                sR2[r1 * 16 + wid] = make_float2(b1b, b2b);
                sRI[r1 * 16 + wid] = (unsigned short)i1b;
            }
        }
        __syncthreads();

        // ---- per-row combine across 16 warps; flag low-margin rows ----
        if (tid < 128) {
            float b = -3.4e38f, b2 = -3.4e38f; int bi = 0;
#pragma unroll
            for (int w = 0; w < 16; w++) {
                float2 v = sR2[tid * 16 + w];
                int oi = sRI[tid * 16 + w];
                bool take = (v.x > b) || (v.x == b && oi < bi);
                float loser = take ? b : v.x;
                b2 = fmaxf(fmaxf(b2, v.y), loser);
                if (take) { b = v.x; bi = oi; }
            }
            sBI[tid] = bi;
            if (b - b2 < TAU) {
                int p = atomicAdd(sNF, 1);
                sLst[p] = tid;
            }
        }
        __syncthreads();
        const int nflag = *sNF;

        // ---- exact fp32 recheck (E staged in 2 halves into SM_E) ----
        if (nflag > 0) {
#pragma unroll 1
            for (int half = 0; half < 2; half++) {
                {   // stage 256 codes fp32, 16B-chunk swizzled
                    int c = tid >> 1;
                    int cb = (tid & 1) * 8;
                    const float4* src = (const float4*)(emb + (size_t)(half * 256 + c) * CD);
                    float4* dst = (float4*)(smem + SM_E + c * 256);
#pragma unroll
                    for (int i = 0; i < 8; i++) {
                        int chunk = cb + i;
                        dst[chunk ^ (c & 15)] = src[chunk];
                    }
                }
                __syncthreads();
#pragma unroll 1
                for (int li = wid; li < nflag; li += 16) {
                    int rowl = sLst[li];
                    const float4* zr = (const float4*)(smem + zoff + rowl * 256);
                    float4 f[16];
#pragma unroll
                    for (int i = 0; i < 16; i++) f[i] = zr[i];
                    float lb = -3.4e38f; int lj = 0;
#pragma unroll 1
                    for (int ii = 0; ii < 8; ii++) {
                        int c = 32 * ii + lane;
                        const float4* er = (const float4*)(smem + SM_E + c * 256);
                        float acc = 0.0f;
#pragma unroll
                        for (int i = 0; i < 16; i++) {
                            float4 e = er[i ^ (c & 15)];
                            acc += f[i].x * e.x + f[i].y * e.y + f[i].z * e.z + f[i].w * e.w;
                        }
                        int j = half * 256 + c;
                        float s = acc - sH[j];
                        if (s > lb) { lb = s; lj = j; }
                    }
#pragma unroll
                    for (int m = 16; m; m >>= 1) {
                        float ob = __shfl_xor_sync(0xffffffffu, lb, m);
                        int   oj = __shfl_xor_sync(0xffffffffu, lj, m);
                        if (ob > lb || (ob == lb && oj < lj)) { lb = ob; lj = oj; }
                    }
                    if (lane == 0) {
                        if (half == 0) {
                            sR2[li] = make_float2(lb, 0.f);
                            sRI[li] = (unsigned short)lj;
                        } else {
                            float2 pv = sR2[li];
                            int pj = sRI[li];
                            if (pv.x > lb || (pv.x == lb && pj < lj)) { lb = pv.x; lj = pj; }
                            sBI[rowl] = lj;
                        }
                    }
                }
                __syncthreads();
            }
        }

        // ---- epilogue: thread t handles row t/4, quarter t%4 ----
        {
            int row = tid >> 2, q = tid & 3;
            int bi = sBI[row];
            size_t rg = (size_t)tile * 128 + row;
            if (q == 0) {
                out[O_IDX + rg] = (float)bi;
                atomicAdd(&sCnt[bi], 1.0f);
            }
            const float4* er = (const float4*)(emb + (size_t)bi * CD + q * 16);
            const float4* zr = (const float4*)(smem + zoff + row * 256 + q * 64);
            float4* oq = (float4*)(out + O_ZQ + rg * CD + q * 16);
            float* es = g_esum + (size_t)bi * CD + q * 16;
#pragma unroll
            for (int i = 0; i < 4; i++) {
                float4 e = er[i], zf = zr[i];
                float d0 = e.x - zf.x, d1 = e.y - zf.y;
                float d2 = e.z - zf.z, d3 = e.w - zf.w;
                sse_acc += d0 * d0 + d1 * d1 + d2 * d2 + d3 * d3;
                oq[i] = make_float4(zf.x + d0, zf.y + d1, zf.z + d2, zf.w + d3);
                asm volatile("red.global.add.v4.f32 [%0], {%1,%2,%3,%4};"
                    :: "l"(es + i * 4), "f"(zf.x), "f"(zf.y), "f"(zf.z), "f"(zf.w)
                    : "memory");
            }
        }
        // loop-top sync protects zoff buffer + smem reuse
    }

    // ---- final merges ----
    __syncthreads();
    {
        float c = sCnt[tid];
        if (c != 0.0f) atomicAdd(&g_counts[tid], c);
    }
#pragma unroll
    for (int m = 16; m; m >>= 1) sse_acc += __shfl_xor_sync(0xffffffffu, sse_acc, m);
    if (lane == 0 && sse_acc != 0.0f) atomicAdd(&g_sse, sse_acc);
}

// ============================================================================
// Kernel 3: finalize EMA + loss
// ============================================================================
__global__ void vq_final(const float* __restrict__ cluster_size,
                         const float* __restrict__ embedding_avg,
                         float* __restrict__ out) {
    __shared__ float red[NC];
    const int j = threadIdx.x;
    float cnt = g_counts[j];
    float ncs = cluster_size[j] * 0.99f + 0.01f * cnt;
    out[O_NCS + j] = ncs;
    red[j] = ncs;
    __syncthreads();
#pragma unroll
    for (int o = NC / 2; o > 0; o >>= 1) {
        if (j < o) red[j] += red[j + o];
        __syncthreads();
    }
    float n  = red[0];
    float cs = (ncs + 1e-6f) / (n + (float)NC * 1e-6f);
#pragma unroll 4
    for (int k = 0; k < CD; k++) {
        float ea = embedding_avg[(size_t)j * CD + k] * 0.99f
                 + 0.01f * g_esum[(size_t)j * CD + k];
        out[O_NAVG + (size_t)j * CD + k] = ea;
        out[O_NEMB + (size_t)j * CD + k] = ea / cs;
    }
    if (j == 0) out[O_LOSS] = 0.25f * g_sse / (float)NELEM;
}

// ============================================================================
extern "C" void kernel_launch(void* const* d_in, const int* in_sizes, int n_in,
                              void* d_out, int out_size) {
    const float* z    = (const float*)d_in[0];
    const float* emb  = (const float*)d_in[1];
    const float* csz  = (const float*)d_in[2];
    const float* eavg = (const float*)d_in[3];
    float* out = (float*)d_out;

    cudaFuncSetAttribute(vq_main, cudaFuncAttributeMaxDynamicSharedMemorySize, SMEM_SZ);
    vq_init<<<64, 512>>>(emb);
    vq_nop1<<<1, 1>>>();
    vq_nop2<<<1, 1>>>();
    vq_main<<<GRID, 512, SMEM_SZ>>>(z, emb, out);
    vq_final<<<1, NC>>>(csz, eavg, out);
}

// round 7
// speedup vs baseline: 1.5713x; 1.5713x over previous
#include <cuda_runtime.h>
#include <cuda_fp16.h>
#include <cstdint>

// ============================================================================
// VectorQuantizerEMA — persistent-CTA HMMA, two-pass (hi+lo) fp16 split,
// candidate-pruned exact fp32 recheck. sm_100-safe PTX only.
// ============================================================================

#define NC      512
#define CD      64
#define NROWS   (64 * 4096)
#define NELEM   (NROWS * CD)
#define NTILES  2048
#define GRID    148
#define TAU     0.06f

#define O_ZQ    ((size_t)0)
#define O_LOSS  ((size_t)16777216)
#define O_IDX   ((size_t)16777217)
#define O_NEMB  ((size_t)17039361)
#define O_NCS   ((size_t)17072129)
#define O_NAVG  ((size_t)17072641)

// ---- device scratch --------------------------------------------------------
__device__ __align__(16) float g_esum[NC * CD];
__device__ __align__(16) unsigned short g_Bh16[NC * CD];  // fp16 E, row-major
__device__ float g_counts[NC];
__device__ float g_h[NC];            // 0.5*||e||^2
__device__ float g_sse;

// ---- smem layout (bytes) ---------------------------------------------------
#define SM_Z0    0        // 32KB raw z tile (double buffer A)
#define SM_Z1    32768    // 32KB raw z tile (double buffer B)
#define SM_AH    65536    // 16KB fp16 A-hi, swizzled
#define SM_AL    81920    // 16KB fp16 A-lo, swizzled
#define SM_R2    98304    // 16KB float2 (best,best2) per (row,warp)
#define SM_RI    114688   // 4KB  u16 best-idx per (row,warp)
#define SM_H     118784   // 2KB
#define SM_CNT   120832   // 2KB
#define SM_BI    122880   // 512B int best idx per row
#define SM_BEST  123392   // 512B float best per row
#define SM_LIST  123904   // 512B flagged rows
#define SM_NFLG  124416
#define SMEM_SZ  124544

__device__ __forceinline__ uint32_t smem_u32(const void* p) {
    uint32_t a;
    asm("{ .reg .u64 t; cvta.to.shared.u64 t, %1; cvt.u32.u64 %0, t; }" : "=r"(a) : "l"(p));
    return a;
}
__device__ __forceinline__ void ldsm_x4(uint32_t a, uint32_t* r) {
    asm volatile("ldmatrix.sync.aligned.m8n8.x4.shared.b16 {%0,%1,%2,%3}, [%4];"
        : "=r"(r[0]), "=r"(r[1]), "=r"(r[2]), "=r"(r[3]) : "r"(a));
}
__device__ __forceinline__ void mma16816(float* c, const uint32_t* a, const uint32_t* b) {
    asm volatile("mma.sync.aligned.m16n8k16.row.col.f32.f16.f16.f32 "
        "{%0,%1,%2,%3}, {%4,%5,%6,%7}, {%8,%9}, {%0,%1,%2,%3};"
        : "+f"(c[0]), "+f"(c[1]), "+f"(c[2]), "+f"(c[3])
        : "r"(a[0]), "r"(a[1]), "r"(a[2]), "r"(a[3]), "r"(b[0]), "r"(b[1]));
}
__device__ __forceinline__ void splitpack(float x, float y, uint32_t& hi, uint32_t& lo) {
    __half hx = __float2half_rn(x), hy = __float2half_rn(y);
    float rx = __half2float(hx), ry = __half2float(hy);
    __half lx = __float2half_rn(x - rx), ly = __float2half_rn(y - ry);
    hi = ((uint32_t)__half_as_ushort(hy) << 16) | __half_as_ushort(hx);
    lo = ((uint32_t)__half_as_ushort(ly) << 16) | __half_as_ushort(lx);
}
__device__ __forceinline__ void cp16(uint32_t d, const void* s) {
    asm volatile("cp.async.cg.shared.global [%0], [%1], 16;" :: "r"(d), "l"(s));
}
#define CP_COMMIT() asm volatile("cp.async.commit_group;")
#define CP_WAIT0()  asm volatile("cp.async.wait_group 0;")

// exact fp32 score for code j against row regs f[16]
__device__ __forceinline__ float exact_score(const float4* __restrict__ f,
                                             const float* __restrict__ emb,
                                             const float* __restrict__ sH, int j) {
    const float4* er = (const float4*)(emb + (size_t)j * CD);
    float acc = 0.0f;
#pragma unroll
    for (int i = 0; i < 16; i++) {
        float4 e = er[i];
        acc += f[i].x * e.x + f[i].y * e.y + f[i].z * e.z + f[i].w * e.w;
    }
    return acc - sH[j];
}

// ============================================================================
// Kernel 1: zero scratch, half-norms, fp16 B
// ============================================================================
__global__ void vq_init(const float* __restrict__ emb) {
    int t = blockIdx.x * blockDim.x + threadIdx.x;   // 64 x 512 = 32768
    if (t < NC * CD) {
        g_esum[t] = 0.0f;
        g_Bh16[t] = __half_as_ushort(__float2half_rn(emb[t]));
    }
    if (t == 0) g_sse = 0.0f;
    if (t < NC) {
        g_counts[t] = 0.0f;
        const float4* e = (const float4*)(emb + (size_t)t * CD);
        float s = 0.0f;
#pragma unroll
        for (int i = 0; i < CD / 4; i++) {
            float4 v = e[i];
            s += v.x * v.x + v.y * v.y + v.z * v.z + v.w * v.w;
        }
        g_h[t] = 0.5f * s;
    }
}

// no-op spacers so ncu -s 5 lands on vq_main
__global__ void vq_nop1() {}
__global__ void vq_nop2() {}

// ============================================================================
// Kernel 2: persistent main. 148 CTAs x 512 thr (16 warps), ~14 tiles each.
// ============================================================================
__global__ void __launch_bounds__(512, 1)
vq_main(const float* __restrict__ z, const float* __restrict__ emb,
        float* __restrict__ out) {
    extern __shared__ __align__(16) char smem[];
    const uint32_t sb32 = smem_u32(smem);
    float*  sH   = (float*)(smem + SM_H);
    float*  sCnt = (float*)(smem + SM_CNT);
    int*    sBI  = (int*)(smem + SM_BI);
    float*  sBest= (float*)(smem + SM_BEST);
    int*    sLst = (int*)(smem + SM_LIST);
    int*    sNF  = (int*)(smem + SM_NFLG);
    float2* sR2  = (float2*)(smem + SM_R2);
    unsigned short* sRI = (unsigned short*)(smem + SM_RI);

    const int tid  = threadIdx.x;
    const int wid  = tid >> 5;
    const int lane = tid & 31;

    // ---- prologue: prefetch first tile, stage h, zero counters ----
    {
        uint32_t dst = sb32 + SM_Z0;
        const char* src = (const char*)(z + (size_t)blockIdx.x * 128 * CD);
#pragma unroll
        for (int i = 0; i < 4; i++) {
            int c = tid + i * 512;
            cp16(dst + c * 16, src + c * 16);
        }
        CP_COMMIT();
    }
    sH[tid] = g_h[tid];
    sCnt[tid] = 0.0f;
    __syncthreads();

    const int jw = wid * 32;
    // ---- hoist B fragments once: 4 nt x 4 ks x {b0,b1} ----
    uint32_t Breg[4][4][2];
#pragma unroll
    for (int nt = 0; nt < 4; nt++) {
        int code = jw + nt * 8 + (lane >> 2);
        const uint32_t* row = (const uint32_t*)(g_Bh16 + (size_t)code * CD);
#pragma unroll
        for (int ks = 0; ks < 4; ks++) {
            int k2 = ks * 8 + (lane & 3);
            Breg[nt][ks][0] = row[k2];
            Breg[nt][ks][1] = row[k2 + 4];
        }
    }
    float hreg[8];
#pragma unroll
    for (int nt = 0; nt < 4; nt++) {
        hreg[nt * 2]     = sH[jw + nt * 8 + 2 * (lane & 3)];
        hreg[nt * 2 + 1] = sH[jw + nt * 8 + 2 * (lane & 3) + 1];
    }

    float sse_acc = 0.0f;
    int it = 0;
#pragma unroll 1
    for (int tile = blockIdx.x; tile < NTILES; tile += GRID, it++) {
        const uint32_t zoff = (it & 1) ? SM_Z1 : SM_Z0;

        CP_WAIT0();
        __syncthreads();

        // ---- convert: raw z (smem) -> fp16 hi/lo, swizzled ----
        {
            int row = tid >> 2, q = tid & 3;
            const float4* zr = (const float4*)(smem + zoff + row * 256 + q * 64);
            float4 v0 = zr[0], v1 = zr[1], v2 = zr[2], v3 = zr[3];
            uint4 H0, L0, H1, L1;
            splitpack(v0.x, v0.y, H0.x, L0.x); splitpack(v0.z, v0.w, H0.y, L0.y);
            splitpack(v1.x, v1.y, H0.z, L0.z); splitpack(v1.z, v1.w, H0.w, L0.w);
            splitpack(v2.x, v2.y, H1.x, L1.x); splitpack(v2.z, v2.w, H1.y, L1.y);
            splitpack(v3.x, v3.y, H1.z, L1.z); splitpack(v3.z, v3.w, H1.w, L1.w);
            uint4* pH = (uint4*)(smem + SM_AH + row * 128);
            uint4* pL = (uint4*)(smem + SM_AL + row * 128);
            int c0 = (2 * q) ^ (row & 7), c1 = (2 * q + 1) ^ (row & 7);
            pH[c0] = H0; pH[c1] = H1;
            pL[c0] = L0; pL[c1] = L1;
        }
        if (tid == 0) *sNF = 0;

        // ---- prefetch next tile (overlaps MMA) ----
        {
            int tn = tile + GRID;
            if (tn < NTILES) {
                uint32_t dst = sb32 + ((it & 1) ? SM_Z0 : SM_Z1);
                const char* src = (const char*)(z + (size_t)tn * 128 * CD);
#pragma unroll
                for (int i = 0; i < 4; i++) {
                    int c = tid + i * 512;
                    cp16(dst + c * 16, src + c * 16);
                }
            }
            CP_COMMIT();
        }
        __syncthreads();

        // ---- MMA mainloop: 8 row-tiles, two passes (hi+lo) into same C ----
#pragma unroll 1
        for (int rt = 0; rt < 8; rt++) {
            uint32_t Ah[16], Al[16];
            {
                int rl = 16 * rt + (lane & 7) + (((lane >> 3) & 1) << 3);
                int ch = (lane >> 4) & 1;
                uint32_t baseH = sb32 + SM_AH + rl * 128;
                int sw = rl & 7;
#pragma unroll
                for (int ks = 0; ks < 4; ks++) {
                    uint32_t off = ((2 * ks + ch) ^ sw) << 4;
                    ldsm_x4(baseH + off, &Ah[ks * 4]);
                    ldsm_x4(baseH + off + (SM_AL - SM_AH), &Al[ks * 4]);
                }
            }
            float C[16];
#pragma unroll
            for (int i = 0; i < 16; i++) C[i] = 0.0f;
#pragma unroll
            for (int nt = 0; nt < 4; nt++)
#pragma unroll
                for (int ks = 0; ks < 4; ks++) {
                    mma16816(&C[nt * 4], &Ah[ks * 4], Breg[nt][ks]);
                    mma16816(&C[nt * 4], &Al[ks * 4], Breg[nt][ks]);
                }

            // ---- extraction: rows g=lane/4 and g+8 ----
            float b1a = -3.4e38f, b2a = -3.4e38f; int i1a = 0;
            float b1b = -3.4e38f, b2b = -3.4e38f; int i1b = 0;
#pragma unroll
            for (int nt = 0; nt < 4; nt++) {
#pragma unroll
                for (int u = 0; u < 2; u++) {
                    int j = jw + nt * 8 + 2 * (lane & 3) + u;
                    float s = C[nt * 4 + u] - hreg[nt * 2 + u];
                    if (s > b1a) { b2a = b1a; b1a = s; i1a = j; }
                    else if (s > b2a) b2a = s;
                    float s2 = C[nt * 4 + 2 + u] - hreg[nt * 2 + u];
                    if (s2 > b1b) { b2b = b1b; b1b = s2; i1b = j; }
                    else if (s2 > b2b) b2b = s2;
                }
            }
#pragma unroll
            for (int m = 1; m <= 2; m <<= 1) {
                float ob  = __shfl_xor_sync(0xffffffffu, b1a, m);
                float ob2 = __shfl_xor_sync(0xffffffffu, b2a, m);
                int   oi  = __shfl_xor_sync(0xffffffffu, i1a, m);
                bool take = (ob > b1a) || (ob == b1a && oi < i1a);
                float loser = take ? b1a : ob;
                b2a = fmaxf(fmaxf(b2a, ob2), loser);
                if (take) { b1a = ob; i1a = oi; }
                ob  = __shfl_xor_sync(0xffffffffu, b1b, m);
                ob2 = __shfl_xor_sync(0xffffffffu, b2b, m);
                oi  = __shfl_xor_sync(0xffffffffu, i1b, m);
                take = (ob > b1b) || (ob == b1b && oi < i1b);
                loser = take ? b1b : ob;
                b2b = fmaxf(fmaxf(b2b, ob2), loser);
                if (take) { b1b = ob; i1b = oi; }
            }
            if ((lane & 3) == 0) {
                int g = lane >> 2;
                int r0 = 16 * rt + g, r1 = r0 + 8;
                sR2[r0 * 16 + wid] = make_float2(b1a, b2a);
                sRI[r0 * 16 + wid] = (unsigned short)i1a;
                sR2[r1 * 16 + wid] = make_float2(b1b, b2b);
                sRI[r1 * 16 + wid] = (unsigned short)i1b;
            }
        }
        __syncthreads();

        // ---- per-row combine; flag low-margin rows ----
        if (tid < 128) {
            float b = -3.4e38f, b2 = -3.4e38f; int bi = 0;
#pragma unroll
            for (int w = 0; w < 16; w++) {
                float2 v = sR2[tid * 16 + w];
                int oi = sRI[tid * 16 + w];
                bool take = (v.x > b) || (v.x == b && oi < bi);
                float loser = take ? b : v.x;
                b2 = fmaxf(fmaxf(b2, v.y), loser);
                if (take) { b = v.x; bi = oi; }
            }
            sBI[tid] = bi;
            sBest[tid] = b;
            if (b - b2 < TAU) {
                int p = atomicAdd(sNF, 1);
                sLst[p] = tid;
            }
        }
        __syncthreads();
        const int nflag = *sNF;

        // ---- candidate-pruned exact recheck (one warp per flagged row) ----
        if (nflag > 0) {
#pragma unroll 1
            for (int li = wid; li < nflag; li += 16) {
                int rowl = sLst[li];
                float thr = sBest[rowl] - TAU;
                float wb = -3.4e38f, wb2 = -3.4e38f; int wic = 0;
                if (lane < 16) {
                    float2 v = sR2[rowl * 16 + lane];
                    wb = v.x; wb2 = v.y;
                    wic = sRI[rowl * 16 + lane];
                }
                unsigned candm  = __ballot_sync(0xffffffffu, wb  >= thr);
                unsigned heavym = __ballot_sync(0xffffffffu, wb  >= thr && wb2 >= thr);
                unsigned lightm = candm & ~heavym;

                float4 f[16];
                {
                    const float4* zr = (const float4*)(smem + zoff + rowl * 256);
#pragma unroll
                    for (int i = 0; i < 16; i++) f[i] = zr[i];
                }
                float lb = -3.4e38f; int lj = NC;
                if (lightm & (1u << lane)) {       // lane<16 by construction
                    lb = exact_score(f, emb, sH, wic);
                    lj = wic;
                }
#pragma unroll 1
                while (heavym) {
                    int c = __ffs(heavym) - 1; heavym &= heavym - 1;
                    int j = 32 * c + lane;
                    float s = exact_score(f, emb, sH, j);
                    if (s > lb || (s == lb && j < lj)) { lb = s; lj = j; }
                }
#pragma unroll
                for (int m = 16; m; m >>= 1) {
                    float ob = __shfl_xor_sync(0xffffffffu, lb, m);
                    int   oj = __shfl_xor_sync(0xffffffffu, lj, m);
                    if (ob > lb || (ob == lb && oj < lj)) { lb = ob; lj = oj; }
                }
                if (lane == 0) sBI[rowl] = lj;
            }
            __syncthreads();
        }

        // ---- epilogue: thread t -> row t/4, quarter t%4 ----
        {
            int row = tid >> 2, q = tid & 3;
            int bi = sBI[row];
            size_t rg = (size_t)tile * 128 + row;
            if (q == 0) {
                out[O_IDX + rg] = (float)bi;
                atomicAdd(&sCnt[bi], 1.0f);
            }
            const float4* er = (const float4*)(emb + (size_t)bi * CD + q * 16);
            const float4* zr = (const float4*)(smem + zoff + row * 256 + q * 64);
            float4* oq = (float4*)(out + O_ZQ + rg * CD + q * 16);
            float* es = g_esum + (size_t)bi * CD + q * 16;
#pragma unroll
            for (int i = 0; i < 4; i++) {
                float4 e = er[i], zf = zr[i];
                float d0 = e.x - zf.x, d1 = e.y - zf.y;
                float d2 = e.z - zf.z, d3 = e.w - zf.w;
                sse_acc += d0 * d0 + d1 * d1 + d2 * d2 + d3 * d3;
                oq[i] = make_float4(zf.x + d0, zf.y + d1, zf.z + d2, zf.w + d3);
                asm volatile("red.global.add.v4.f32 [%0], {%1,%2,%3,%4};"
                    :: "l"(es + i * 4), "f"(zf.x), "f"(zf.y), "f"(zf.z), "f"(zf.w)
                    : "memory");
            }
        }
    }

    // ---- final merges ----
    __syncthreads();
    {
        float c = sCnt[tid];
        if (c != 0.0f) atomicAdd(&g_counts[tid], c);
    }
#pragma unroll
    for (int m = 16; m; m >>= 1) sse_acc += __shfl_xor_sync(0xffffffffu, sse_acc, m);
    if (lane == 0 && sse_acc != 0.0f) atomicAdd(&g_sse, sse_acc);
}

// ============================================================================
// Kernel 3: finalize EMA + loss
// ============================================================================
__global__ void vq_final(const float* __restrict__ cluster_size,
                         const float* __restrict__ embedding_avg,
                         float* __restrict__ out) {
    __shared__ float red[NC];
    const int j = threadIdx.x;
    float cnt = g_counts[j];
    float ncs = cluster_size[j] * 0.99f + 0.01f * cnt;
    out[O_NCS + j] = ncs;
    red[j] = ncs;
    __syncthreads();
#pragma unroll
    for (int o = NC / 2; o > 0; o >>= 1) {
        if (j < o) red[j] += red[j + o];
        __syncthreads();
    }
    float n  = red[0];
    float cs = (ncs + 1e-6f) / (n + (float)NC * 1e-6f);
#pragma unroll 4
    for (int k = 0; k < CD; k++) {
        float ea = embedding_avg[(size_t)j * CD + k] * 0.99f
                 + 0.01f * g_esum[(size_t)j * CD + k];
        out[O_NAVG + (size_t)j * CD + k] = ea;
        out[O_NEMB + (size_t)j * CD + k] = ea / cs;
    }
    if (j == 0) out[O_LOSS] = 0.25f * g_sse / (float)NELEM;
}

// ============================================================================
extern "C" void kernel_launch(void* const* d_in, const int* in_sizes, int n_in,
                              void* d_out, int out_size) {
    const float* z    = (const float*)d_in[0];
    const float* emb  = (const float*)d_in[1];
    const float* csz  = (const float*)d_in[2];
    const float* eavg = (const float*)d_in[3];
    float* out = (float*)d_out;

    cudaFuncSetAttribute(vq_main, cudaFuncAttributeMaxDynamicSharedMemorySize, SMEM_SZ);
    vq_init<<<64, 512>>>(emb);
    vq_nop1<<<1, 1>>>();
    vq_nop2<<<1, 1>>>();
    vq_main<<<GRID, 512, SMEM_SZ>>>(z, emb, out);
    vq_final<<<1, NC>>>(csz, eavg, out);
}

// round 8
// speedup vs baseline: 1.8973x; 1.2075x over previous
#include <cuda_runtime.h>
#include <cuda_fp16.h>
#include <cstdint>

// ============================================================================
// VectorQuantizerEMA — persistent-CTA HMMA, single-pass fp16 scoring with
// candidate-pruned exact fp32 recheck (TAU >= 2*eps guarantee).
// ============================================================================

#define NC      512
#define CD      64
#define NROWS   (64 * 4096)
#define NELEM   (NROWS * CD)
#define NTILES  2048
#define GRID    148
#define TAU     0.15f

#define O_ZQ    ((size_t)0)
#define O_LOSS  ((size_t)16777216)
#define O_IDX   ((size_t)16777217)
#define O_NEMB  ((size_t)17039361)
#define O_NCS   ((size_t)17072129)
#define O_NAVG  ((size_t)17072641)

// ---- device scratch --------------------------------------------------------
__device__ __align__(16) float g_esum[NC * CD];
__device__ __align__(16) unsigned short g_Bh16[NC * CD];  // fp16 E, row-major
__device__ float g_counts[NC];
__device__ float g_h[NC];            // 0.5*||e||^2
__device__ float g_sse;

// ---- smem layout (bytes) ---------------------------------------------------
#define SM_Z     0        // 32KB raw z tile (single buffer)
#define SM_AH    32768    // 16KB fp16 A-hi, swizzled
#define SM_R2    49152    // 16KB float2 (best,best2) per (row,warp)
#define SM_RI    65536    // 4KB  u16 best-idx per (row,warp)
#define SM_H     69632    // 2KB
#define SM_CNT   71680    // 2KB
#define SM_BI    73728    // 512B
#define SM_BEST  74240    // 512B
#define SM_LIST  74752    // 512B
#define SM_NFLG  75264
#define SMEM_SZ  75392

__device__ __forceinline__ uint32_t smem_u32(const void* p) {
    uint32_t a;
    asm("{ .reg .u64 t; cvta.to.shared.u64 t, %1; cvt.u32.u64 %0, t; }" : "=r"(a) : "l"(p));
    return a;
}
__device__ __forceinline__ void ldsm_x4(uint32_t a, uint32_t* r) {
    asm volatile("ldmatrix.sync.aligned.m8n8.x4.shared.b16 {%0,%1,%2,%3}, [%4];"
        : "=r"(r[0]), "=r"(r[1]), "=r"(r[2]), "=r"(r[3]) : "r"(a));
}
__device__ __forceinline__ void mma16816(float* c, const uint32_t* a, const uint32_t* b) {
    asm volatile("mma.sync.aligned.m16n8k16.row.col.f32.f16.f16.f32 "
        "{%0,%1,%2,%3}, {%4,%5,%6,%7}, {%8,%9}, {%0,%1,%2,%3};"
        : "+f"(c[0]), "+f"(c[1]), "+f"(c[2]), "+f"(c[3])
        : "r"(a[0]), "r"(a[1]), "r"(a[2]), "r"(a[3]), "r"(b[0]), "r"(b[1]));
}
__device__ __forceinline__ uint32_t packh(float x, float y) {
    __half2 h = __floats2half2_rn(x, y);
    return *(uint32_t*)&h;
}
__device__ __forceinline__ void cp16(uint32_t d, const void* s) {
    asm volatile("cp.async.cg.shared.global [%0], [%1], 16;" :: "r"(d), "l"(s));
}
#define CP_COMMIT() asm volatile("cp.async.commit_group;")
#define CP_WAIT0()  asm volatile("cp.async.wait_group 0;")

// exact fp32 score for code j against row regs f[16]
__device__ __forceinline__ float exact_score(const float4* __restrict__ f,
                                             const float* __restrict__ emb,
                                             const float* __restrict__ sH, int j) {
    const float4* er = (const float4*)(emb + (size_t)j * CD);
    float acc = 0.0f;
#pragma unroll
    for (int i = 0; i < 16; i++) {
        float4 e = er[i];
        acc += f[i].x * e.x + f[i].y * e.y + f[i].z * e.z + f[i].w * e.w;
    }
    return acc - sH[j];
}

// ============================================================================
// Kernel 1: zero scratch, half-norms, fp16 B
// ============================================================================
__global__ void vq_init(const float* __restrict__ emb) {
    int t = blockIdx.x * blockDim.x + threadIdx.x;   // 64 x 512 = 32768
    if (t < NC * CD) {
        g_esum[t] = 0.0f;
        g_Bh16[t] = __half_as_ushort(__float2half_rn(emb[t]));
    }
    if (t == 0) g_sse = 0.0f;
    if (t < NC) {
        g_counts[t] = 0.0f;
        const float4* e = (const float4*)(emb + (size_t)t * CD);
        float s = 0.0f;
#pragma unroll
        for (int i = 0; i < CD / 4; i++) {
            float4 v = e[i];
            s += v.x * v.x + v.y * v.y + v.z * v.z + v.w * v.w;
        }
        g_h[t] = 0.5f * s;
    }
}

// no-op spacers so ncu -s 5 lands on vq_main
__global__ void vq_nop1() {}
__global__ void vq_nop2() {}

// ============================================================================
// Kernel 2: persistent main. 148 CTAs x 512 thr (16 warps), ~14 tiles each.
// Warp w owns codes [32w,32w+32); B fragments register-resident all kernel.
// z tile: cp.async -> smem -> thread-private regs (convert + epilogue).
// ============================================================================
__global__ void __launch_bounds__(512, 1)
vq_main(const float* __restrict__ z, const float* __restrict__ emb,
        float* __restrict__ out) {
    extern __shared__ __align__(16) char smem[];
    const uint32_t sb32 = smem_u32(smem);
    float*  sH   = (float*)(smem + SM_H);
    float*  sCnt = (float*)(smem + SM_CNT);
    int*    sBI  = (int*)(smem + SM_BI);
    float*  sBest= (float*)(smem + SM_BEST);
    int*    sLst = (int*)(smem + SM_LIST);
    int*    sNF  = (int*)(smem + SM_NFLG);
    float2* sR2  = (float2*)(smem + SM_R2);
    unsigned short* sRI = (unsigned short*)(smem + SM_RI);

    const int tid  = threadIdx.x;
    const int wid  = tid >> 5;
    const int lane = tid & 31;

    // ---- prologue: prefetch first tile; stage h; zero counters ----
    {
        uint32_t dst = sb32 + SM_Z;
        const char* src = (const char*)(z + (size_t)blockIdx.x * 128 * CD);
#pragma unroll
        for (int i = 0; i < 4; i++) {
            int c = tid + i * 512;
            cp16(dst + c * 16, src + c * 16);
        }
        CP_COMMIT();
    }
    sH[tid] = g_h[tid];
    sCnt[tid] = 0.0f;

    const int jw = wid * 32;
    // ---- hoist B fragments once: 4 nt x 4 ks x {b0,b1} ----
    uint32_t Breg[4][4][2];
#pragma unroll
    for (int nt = 0; nt < 4; nt++) {
        int code = jw + nt * 8 + (lane >> 2);
        const uint32_t* row = (const uint32_t*)(g_Bh16 + (size_t)code * CD);
#pragma unroll
        for (int ks = 0; ks < 4; ks++) {
            int k2 = ks * 8 + (lane & 3);
            Breg[nt][ks][0] = row[k2];
            Breg[nt][ks][1] = row[k2 + 4];
        }
    }
    __syncthreads();
    float hreg[8];
#pragma unroll
    for (int nt = 0; nt < 4; nt++) {
        hreg[nt * 2]     = sH[jw + nt * 8 + 2 * (lane & 3)];
        hreg[nt * 2 + 1] = sH[jw + nt * 8 + 2 * (lane & 3) + 1];
    }

    const int myrow = tid >> 2;          // epilogue/convert row
    const int myq   = tid & 3;           // quarter within row

    float sse_acc = 0.0f;
#pragma unroll 1
    for (int tile = blockIdx.x; tile < NTILES; tile += GRID) {
        CP_WAIT0();
        __syncthreads();                 // z buffer resident; prev phase done

        // ---- pull my z quarter into regs; convert -> AH (swizzled) ----
        float4 zreg[4];
        {
            const float4* zr = (const float4*)(smem + SM_Z + myrow * 256 + myq * 64);
            zreg[0] = zr[0]; zreg[1] = zr[1]; zreg[2] = zr[2]; zreg[3] = zr[3];
            uint4 H0, H1;
            H0.x = packh(zreg[0].x, zreg[0].y); H0.y = packh(zreg[0].z, zreg[0].w);
            H0.z = packh(zreg[1].x, zreg[1].y); H0.w = packh(zreg[1].z, zreg[1].w);
            H1.x = packh(zreg[2].x, zreg[2].y); H1.y = packh(zreg[2].z, zreg[2].w);
            H1.z = packh(zreg[3].x, zreg[3].y); H1.w = packh(zreg[3].z, zreg[3].w);
            uint4* pH = (uint4*)(smem + SM_AH + myrow * 128);
            pH[(2 * myq) ^ (myrow & 7)]     = H0;
            pH[(2 * myq + 1) ^ (myrow & 7)] = H1;
        }
        if (tid == 0) *sNF = 0;
        __syncthreads();                 // AH ready; z buffer fully consumed

        // ---- prefetch next tile into the SAME buffer (overlaps MMA) ----
        {
            int tn = tile + GRID;
            if (tn < NTILES) {
                uint32_t dst = sb32 + SM_Z;
                const char* src = (const char*)(z + (size_t)tn * 128 * CD);
#pragma unroll
                for (int i = 0; i < 4; i++) {
                    int c = tid + i * 512;
                    cp16(dst + c * 16, src + c * 16);
                }
            }
            CP_COMMIT();
        }

        // ---- MMA mainloop: 8 row-tiles, single fp16 pass ----
#pragma unroll 1
        for (int rt = 0; rt < 8; rt++) {
            uint32_t Ah[16];
            {
                int rl = 16 * rt + (lane & 7) + (((lane >> 3) & 1) << 3);
                int ch = (lane >> 4) & 1;
                uint32_t baseH = sb32 + SM_AH + rl * 128;
                int sw = rl & 7;
#pragma unroll
                for (int ks = 0; ks < 4; ks++)
                    ldsm_x4(baseH + (((2 * ks + ch) ^ sw) << 4), &Ah[ks * 4]);
            }
            float C[16];
#pragma unroll
            for (int i = 0; i < 16; i++) C[i] = 0.0f;
#pragma unroll
            for (int nt = 0; nt < 4; nt++)
#pragma unroll
                for (int ks = 0; ks < 4; ks++)
                    mma16816(&C[nt * 4], &Ah[ks * 4], Breg[nt][ks]);

            // ---- extraction: rows g=lane/4 and g+8 ----
            float b1a = -3.4e38f, b2a = -3.4e38f; int i1a = 0;
            float b1b = -3.4e38f, b2b = -3.4e38f; int i1b = 0;
#pragma unroll
            for (int nt = 0; nt < 4; nt++) {
#pragma unroll
                for (int u = 0; u < 2; u++) {
                    int j = jw + nt * 8 + 2 * (lane & 3) + u;
                    float s = C[nt * 4 + u] - hreg[nt * 2 + u];
                    if (s > b1a) { b2a = b1a; b1a = s; i1a = j; }
                    else if (s > b2a) b2a = s;
                    float s2 = C[nt * 4 + 2 + u] - hreg[nt * 2 + u];
                    if (s2 > b1b) { b2b = b1b; b1b = s2; i1b = j; }
                    else if (s2 > b2b) b2b = s2;
                }
            }
#pragma unroll
            for (int m = 1; m <= 2; m <<= 1) {
                float ob  = __shfl_xor_sync(0xffffffffu, b1a, m);
                float ob2 = __shfl_xor_sync(0xffffffffu, b2a, m);
                int   oi  = __shfl_xor_sync(0xffffffffu, i1a, m);
                bool take = (ob > b1a) || (ob == b1a && oi < i1a);
                float loser = take ? b1a : ob;
                b2a = fmaxf(fmaxf(b2a, ob2), loser);
                if (take) { b1a = ob; i1a = oi; }
                ob  = __shfl_xor_sync(0xffffffffu, b1b, m);
                ob2 = __shfl_xor_sync(0xffffffffu, b2b, m);
                oi  = __shfl_xor_sync(0xffffffffu, i1b, m);
                take = (ob > b1b) || (ob == b1b && oi < i1b);
                loser = take ? b1b : ob;
                b2b = fmaxf(fmaxf(b2b, ob2), loser);
                if (take) { b1b = ob; i1b = oi; }
            }
            if ((lane & 3) == 0) {
                int g = lane >> 2;
                int r0 = 16 * rt + g, r1 = r0 + 8;
                sR2[r0 * 16 + wid] = make_float2(b1a, b2a);
                sRI[r0 * 16 + wid] = (unsigned short)i1a;
                sR2[r1 * 16 + wid] = make_float2(b1b, b2b);
                sRI[r1 * 16 + wid] = (unsigned short)i1b;
            }
        }
        __syncthreads();

        // ---- per-row combine; flag low-margin rows ----
        if (tid < 128) {
            float b = -3.4e38f, b2 = -3.4e38f; int bi = 0;
#pragma unroll
            for (int w = 0; w < 16; w++) {
                float2 v = sR2[tid * 16 + w];
                int oi = sRI[tid * 16 + w];
                bool take = (v.x > b) || (v.x == b && oi < bi);
                float loser = take ? b : v.x;
                b2 = fmaxf(fmaxf(b2, v.y), loser);
                if (take) { b = v.x; bi = oi; }
            }
            sBI[tid] = bi;
            sBest[tid] = b;
            if (b - b2 < TAU) {
                int p = atomicAdd(sNF, 1);
                sLst[p] = tid;
            }
        }
        __syncthreads();
        const int nflag = *sNF;

        // ---- candidate-pruned exact recheck (one warp per flagged row) ----
        if (nflag > 0) {
#pragma unroll 1
            for (int li = wid; li < nflag; li += 16) {
                int rowl = sLst[li];
                float thr = sBest[rowl] - TAU;
                float wb = -3.4e38f, wb2 = -3.4e38f; int wic = 0;
                if (lane < 16) {
                    float2 v = sR2[rowl * 16 + lane];
                    wb = v.x; wb2 = v.y;
                    wic = sRI[rowl * 16 + lane];
                }
                unsigned candm  = __ballot_sync(0xffffffffu, wb  >= thr);
                unsigned heavym = __ballot_sync(0xffffffffu, wb  >= thr && wb2 >= thr);
                unsigned lightm = candm & ~heavym;

                float4 f[16];
                {   // flagged row's z from gmem (L2-hot)
                    const float4* zr =
                        (const float4*)(z + ((size_t)tile * 128 + rowl) * CD);
#pragma unroll
                    for (int i = 0; i < 16; i++) f[i] = zr[i];
                }
                float lb = -3.4e38f; int lj = NC;
                if (lightm & (1u << lane)) {
                    lb = exact_score(f, emb, sH, wic);
                    lj = wic;
                }
#pragma unroll 1
                while (heavym) {
                    int c = __ffs(heavym) - 1; heavym &= heavym - 1;
                    int j = 32 * c + lane;
                    float s = exact_score(f, emb, sH, j);
                    if (s > lb || (s == lb && j < lj)) { lb = s; lj = j; }
                }
#pragma unroll
                for (int m = 16; m; m >>= 1) {
                    float ob = __shfl_xor_sync(0xffffffffu, lb, m);
                    int   oj = __shfl_xor_sync(0xffffffffu, lj, m);
                    if (ob > lb || (ob == lb && oj < lj)) { lb = ob; lj = oj; }
                }
                if (lane == 0) sBI[rowl] = lj;
            }
            __syncthreads();
        }

        // ---- epilogue: thread t -> row t/4, quarter t%4 (z from regs) ----
        {
            int bi = sBI[myrow];
            size_t rg = (size_t)tile * 128 + myrow;
            if (myq == 0) {
                out[O_IDX + rg] = (float)bi;
                atomicAdd(&sCnt[bi], 1.0f);
            }
            const float4* er = (const float4*)(emb + (size_t)bi * CD + myq * 16);
            float4* oq = (float4*)(out + O_ZQ + rg * CD + myq * 16);
            float* es = g_esum + (size_t)bi * CD + myq * 16;
#pragma unroll
            for (int i = 0; i < 4; i++) {
                float4 e = er[i], zf = zreg[i];
                float d0 = e.x - zf.x, d1 = e.y - zf.y;
                float d2 = e.z - zf.z, d3 = e.w - zf.w;
                sse_acc += d0 * d0 + d1 * d1 + d2 * d2 + d3 * d3;
                oq[i] = make_float4(zf.x + d0, zf.y + d1, zf.z + d2, zf.w + d3);
                asm volatile("red.global.add.v4.f32 [%0], {%1,%2,%3,%4};"
                    :: "l"(es + i * 4), "f"(zf.x), "f"(zf.y), "f"(zf.z), "f"(zf.w)
                    : "memory");
            }
        }
    }

    // ---- final merges ----
    __syncthreads();
    {
        float c = sCnt[tid];
        if (c != 0.0f) atomicAdd(&g_counts[tid], c);
    }
#pragma unroll
    for (int m = 16; m; m >>= 1) sse_acc += __shfl_xor_sync(0xffffffffu, sse_acc, m);
    if (lane == 0 && sse_acc != 0.0f) atomicAdd(&g_sse, sse_acc);
}

// ============================================================================
// Kernel 3: finalize EMA + loss
// ============================================================================
__global__ void vq_final(const float* __restrict__ cluster_size,
                         const float* __restrict__ embedding_avg,
                         float* __restrict__ out) {
    __shared__ float red[NC];
    const int j = threadIdx.x;
    float cnt = g_counts[j];
    float ncs = cluster_size[j] * 0.99f + 0.01f * cnt;
    out[O_NCS + j] = ncs;
    red[j] = ncs;
    __syncthreads();
#pragma unroll
    for (int o = NC / 2; o > 0; o >>= 1) {
        if (j < o) red[j] += red[j + o];
        __syncthreads();
    }
    float n  = red[0];
    float cs = (ncs + 1e-6f) / (n + (float)NC * 1e-6f);
#pragma unroll 4
    for (int k = 0; k < CD; k++) {
        float ea = embedding_avg[(size_t)j * CD + k] * 0.99f
                 + 0.01f * g_esum[(size_t)j * CD + k];
        out[O_NAVG + (size_t)j * CD + k] = ea;
        out[O_NEMB + (size_t)j * CD + k] = ea / cs;
    }
    if (j == 0) out[O_LOSS] = 0.25f * g_sse / (float)NELEM;
}

// ============================================================================
extern "C" void kernel_launch(void* const* d_in, const int* in_sizes, int n_in,
                              void* d_out, int out_size) {
    const float* z    = (const float*)d_in[0];
    const float* emb  = (const float*)d_in[1];
    const float* csz  = (const float*)d_in[2];
    const float* eavg = (const float*)d_in[3];
    float* out = (float*)d_out;

    cudaFuncSetAttribute(vq_main, cudaFuncAttributeMaxDynamicSharedMemorySize, SMEM_SZ);
    vq_init<<<64, 512>>>(emb);
    vq_nop1<<<1, 1>>>();
    vq_nop2<<<1, 1>>>();
    vq_main<<<GRID, 512, SMEM_SZ>>>(z, emb, out);
    vq_final<<<1, NC>>>(csz, eavg, out);
}

// round 9
// speedup vs baseline: 1.9986x; 1.0533x over previous
#include <cuda_runtime.h>
#include <cuda_fp16.h>
#include <cstdint>

// ============================================================================
// VectorQuantizerEMA — persistent 2-CTA/SM HMMA, single-pass fp16 scoring,
// candidate-pruned exact fp32 recheck (TAU >= 2*eps guarantee).
// ============================================================================

#define NC      512
#define CD      64
#define NROWS   (64 * 4096)
#define NELEM   (NROWS * CD)
#define TROWS   64
#define NTILES  (NROWS / TROWS)     // 4096
#define GRID    296                 // 2 CTAs per SM
#define TAU     0.15f

#define O_ZQ    ((size_t)0)
#define O_LOSS  ((size_t)16777216)
#define O_IDX   ((size_t)16777217)
#define O_NEMB  ((size_t)17039361)
#define O_NCS   ((size_t)17072129)
#define O_NAVG  ((size_t)17072641)

// ---- device scratch --------------------------------------------------------
__device__ __align__(16) float g_esum[NC * CD];
__device__ __align__(16) unsigned short g_Bh16[NC * CD];  // fp16 E row-major
__device__ float g_counts[NC];
__device__ float g_h[NC];            // 0.5*||e||^2
__device__ float g_sse;

// ---- smem layout (bytes, per CTA) ------------------------------------------
#define SM_Z0    0        // 16KB raw z tile buf A
#define SM_Z1    16384    // 16KB raw z tile buf B
#define SM_AH    32768    // 8KB fp16 A, swizzled
#define SM_R2    40960    // 4KB float2 (best,best2) per (row,warp)  64x8
#define SM_RI    45056    // 1KB u16 idx per (row,warp)
#define SM_H     46080    // 2KB
#define SM_CNT   48128    // 2KB
#define SM_BI    50176    // 256B
#define SM_BEST  50432    // 256B
#define SM_LIST  50688    // 256B
#define SM_NFLG  50944
#define SMEM_SZ  51072

__device__ __forceinline__ uint32_t smem_u32(const void* p) {
    uint32_t a;
    asm("{ .reg .u64 t; cvta.to.shared.u64 t, %1; cvt.u32.u64 %0, t; }" : "=r"(a) : "l"(p));
    return a;
}
__device__ __forceinline__ void ldsm_x4(uint32_t a, uint32_t* r) {
    asm volatile("ldmatrix.sync.aligned.m8n8.x4.shared.b16 {%0,%1,%2,%3}, [%4];"
        : "=r"(r[0]), "=r"(r[1]), "=r"(r[2]), "=r"(r[3]) : "r"(a));
}
__device__ __forceinline__ void mma16816(float* c, const uint32_t* a, const uint32_t* b) {
    asm volatile("mma.sync.aligned.m16n8k16.row.col.f32.f16.f16.f32 "
        "{%0,%1,%2,%3}, {%4,%5,%6,%7}, {%8,%9}, {%0,%1,%2,%3};"
        : "+f"(c[0]), "+f"(c[1]), "+f"(c[2]), "+f"(c[3])
        : "r"(a[0]), "r"(a[1]), "r"(a[2]), "r"(a[3]), "r"(b[0]), "r"(b[1]));
}
__device__ __forceinline__ uint32_t packh(float x, float y) {
    __half2 h = __floats2half2_rn(x, y);
    return *(uint32_t*)&h;
}
__device__ __forceinline__ void cp16(uint32_t d, const void* s) {
    asm volatile("cp.async.cg.shared.global [%0], [%1], 16;" :: "r"(d), "l"(s));
}
#define CP_COMMIT() asm volatile("cp.async.commit_group;")
#define CP_WAIT0()  asm volatile("cp.async.wait_group 0;")

__device__ __forceinline__ float exact_score(const float4* __restrict__ f,
                                             const float* __restrict__ emb,
                                             const float* __restrict__ sH, int j) {
    const float4* er = (const float4*)(emb + (size_t)j * CD);
    float acc = 0.0f;
#pragma unroll
    for (int i = 0; i < 16; i++) {
        float4 e = er[i];
        acc += f[i].x * e.x + f[i].y * e.y + f[i].z * e.z + f[i].w * e.w;
    }
    return acc - sH[j];
}

// ============================================================================
// Kernel 1: zero scratch, half-norms, fp16 B
// ============================================================================
__global__ void vq_init(const float* __restrict__ emb) {
    int t = blockIdx.x * blockDim.x + threadIdx.x;   // 32768
    if (t < NC * CD) {
        g_esum[t] = 0.0f;
        g_Bh16[t] = __half_as_ushort(__float2half_rn(emb[t]));
    }
    if (t == 0) g_sse = 0.0f;
    if (t < NC) {
        g_counts[t] = 0.0f;
        const float4* e = (const float4*)(emb + (size_t)t * CD);
        float s = 0.0f;
#pragma unroll
        for (int i = 0; i < CD / 4; i++) {
            float4 v = e[i];
            s += v.x * v.x + v.y * v.y + v.z * v.z + v.w * v.w;
        }
        g_h[t] = 0.5f * s;
    }
}

// no-op spacers so ncu -s 5 lands on vq_main
__global__ void vq_nop1() {}
__global__ void vq_nop2() {}

// ============================================================================
// Kernel 2: persistent main. 296 CTAs x 256 thr (8 warps), 64-row tiles.
// Warp w owns codes [64w, 64w+64) in 8 n-tiles (two 4-nt halves).
// ============================================================================
__global__ void __launch_bounds__(256, 2)
vq_main(const float* __restrict__ z, const float* __restrict__ emb,
        float* __restrict__ out) {
    extern __shared__ __align__(16) char smem[];
    const uint32_t sb32 = smem_u32(smem);
    float*  sH   = (float*)(smem + SM_H);
    float*  sCnt = (float*)(smem + SM_CNT);
    int*    sBI  = (int*)(smem + SM_BI);
    float*  sBest= (float*)(smem + SM_BEST);
    int*    sLst = (int*)(smem + SM_LIST);
    int*    sNF  = (int*)(smem + SM_NFLG);
    float2* sR2  = (float2*)(smem + SM_R2);
    unsigned short* sRI = (unsigned short*)(smem + SM_RI);

    const int tid  = threadIdx.x;
    const int wid  = tid >> 5;      // 0..7
    const int lane = tid & 31;

    // ---- prologue: prefetch first tile; stage h; zero counters ----
    {
        uint32_t dst = sb32 + SM_Z0;
        const char* src = (const char*)(z + (size_t)blockIdx.x * TROWS * CD);
#pragma unroll
        for (int i = 0; i < 4; i++) {
            int c = tid + i * 256;
            cp16(dst + c * 16, src + c * 16);
        }
        CP_COMMIT();
    }
#pragma unroll
    for (int i = 0; i < 2; i++) {
        sH[tid + 256 * i] = g_h[tid + 256 * i];
        sCnt[tid + 256 * i] = 0.0f;
    }

    const int jw = wid * 64;
    // ---- hoist B fragments once: 8 nt x 4 ks x {b0,b1} = 64 regs ----
    uint32_t Breg[8][4][2];
#pragma unroll
    for (int nt = 0; nt < 8; nt++) {
        int code = jw + nt * 8 + (lane >> 2);
        const uint32_t* row = (const uint32_t*)(g_Bh16 + (size_t)code * CD);
#pragma unroll
        for (int ks = 0; ks < 4; ks++) {
            int k2 = ks * 8 + (lane & 3);
            Breg[nt][ks][0] = row[k2];
            Breg[nt][ks][1] = row[k2 + 4];
        }
    }
    __syncthreads();

    const int myrow = tid >> 2;          // 0..63
    const int myq   = tid & 3;

    float sse_acc = 0.0f;
    int it = 0;
#pragma unroll 1
    for (int tile = blockIdx.x; tile < NTILES; tile += GRID, it++) {
        const uint32_t zoff = (it & 1) ? SM_Z1 : SM_Z0;

        CP_WAIT0();
        __syncthreads();                 // cur z resident; prev phases done

        // ---- convert: z quarter -> fp16 AH (swizzled) ----
        {
            const float4* zr = (const float4*)(smem + zoff + myrow * 256 + myq * 64);
            float4 v0 = zr[0], v1 = zr[1], v2 = zr[2], v3 = zr[3];
            uint4 H0, H1;
            H0.x = packh(v0.x, v0.y); H0.y = packh(v0.z, v0.w);
            H0.z = packh(v1.x, v1.y); H0.w = packh(v1.z, v1.w);
            H1.x = packh(v2.x, v2.y); H1.y = packh(v2.z, v2.w);
            H1.z = packh(v3.x, v3.y); H1.w = packh(v3.z, v3.w);
            uint4* pH = (uint4*)(smem + SM_AH + myrow * 128);
            pH[(2 * myq) ^ (myrow & 7)]     = H0;
            pH[(2 * myq + 1) ^ (myrow & 7)] = H1;
        }
        if (tid == 0) *sNF = 0;
        __syncthreads();

        // ---- prefetch next tile into other buffer (overlaps MMA) ----
        {
            int tn = tile + GRID;
            if (tn < NTILES) {
                uint32_t dst = sb32 + ((it & 1) ? SM_Z0 : SM_Z1);
                const char* src = (const char*)(z + (size_t)tn * TROWS * CD);
#pragma unroll
                for (int i = 0; i < 4; i++) {
                    int c = tid + i * 256;
                    cp16(dst + c * 16, src + c * 16);
                }
            }
            CP_COMMIT();
        }

        // ---- MMA mainloop: 4 row-tiles x two 4-nt halves ----
#pragma unroll 1
        for (int rt = 0; rt < 4; rt++) {
            uint32_t Ah[16];
            {
                int rl = 16 * rt + (lane & 7) + (((lane >> 3) & 1) << 3);
                int ch = (lane >> 4) & 1;
                uint32_t baseH = sb32 + SM_AH + rl * 128;
                int sw = rl & 7;
#pragma unroll
                for (int ks = 0; ks < 4; ks++)
                    ldsm_x4(baseH + (((2 * ks + ch) ^ sw) << 4), &Ah[ks * 4]);
            }
            float b1a = -3.4e38f, b2a = -3.4e38f; int i1a = 0;
            float b1b = -3.4e38f, b2b = -3.4e38f; int i1b = 0;
#pragma unroll
            for (int h = 0; h < 2; h++) {
                float C[16];
#pragma unroll
                for (int i = 0; i < 16; i++) C[i] = 0.0f;
#pragma unroll
                for (int n4 = 0; n4 < 4; n4++)
#pragma unroll
                    for (int ks = 0; ks < 4; ks++)
                        mma16816(&C[n4 * 4], &Ah[ks * 4], Breg[h * 4 + n4][ks]);

#pragma unroll
                for (int n4 = 0; n4 < 4; n4++) {
#pragma unroll
                    for (int u = 0; u < 2; u++) {
                        int j = jw + h * 32 + n4 * 8 + 2 * (lane & 3) + u;
                        float hh = sH[j];
                        float s = C[n4 * 4 + u] - hh;
                        if (s > b1a) { b2a = b1a; b1a = s; i1a = j; }
                        else if (s > b2a) b2a = s;
                        float s2 = C[n4 * 4 + 2 + u] - hh;
                        if (s2 > b1b) { b2b = b1b; b1b = s2; i1b = j; }
                        else if (s2 > b2b) b2b = s2;
                    }
                }
            }
#pragma unroll
            for (int m = 1; m <= 2; m <<= 1) {
                float ob  = __shfl_xor_sync(0xffffffffu, b1a, m);
                float ob2 = __shfl_xor_sync(0xffffffffu, b2a, m);
                int   oi  = __shfl_xor_sync(0xffffffffu, i1a, m);
                bool take = (ob > b1a) || (ob == b1a && oi < i1a);
                float loser = take ? b1a : ob;
                b2a = fmaxf(fmaxf(b2a, ob2), loser);
                if (take) { b1a = ob; i1a = oi; }
                ob  = __shfl_xor_sync(0xffffffffu, b1b, m);
                ob2 = __shfl_xor_sync(0xffffffffu, b2b, m);
                oi  = __shfl_xor_sync(0xffffffffu, i1b, m);
                take = (ob > b1b) || (ob == b1b && oi < i1b);
                loser = take ? b1b : ob;
                b2b = fmaxf(fmaxf(b2b, ob2), loser);
                if (take) { b1b = ob; i1b = oi; }
            }
            if ((lane & 3) == 0) {
                int g = lane >> 2;
                int r0 = 16 * rt + g, r1 = r0 + 8;
                sR2[r0 * 8 + wid] = make_float2(b1a, b2a);
                sRI[r0 * 8 + wid] = (unsigned short)i1a;
                sR2[r1 * 8 + wid] = make_float2(b1b, b2b);
                sRI[r1 * 8 + wid] = (unsigned short)i1b;
            }
        }
        __syncthreads();

        // ---- per-row combine across 8 warps; flag low-margin rows ----
        if (tid < TROWS) {
            float b = -3.4e38f, b2 = -3.4e38f; int bi = 0;
#pragma unroll
            for (int w = 0; w < 8; w++) {
                float2 v = sR2[tid * 8 + w];
                int oi = sRI[tid * 8 + w];
                bool take = (v.x > b) || (v.x == b && oi < bi);
                float loser = take ? b : v.x;
                b2 = fmaxf(fmaxf(b2, v.y), loser);
                if (take) { b = v.x; bi = oi; }
            }
            sBI[tid] = bi;
            sBest[tid] = b;
            if (b - b2 < TAU) {
                int p = atomicAdd(sNF, 1);
                sLst[p] = tid;
            }
        }
        __syncthreads();
        const int nflag = *sNF;

        // ---- candidate-pruned exact recheck (one warp per flagged row) ----
        if (nflag > 0) {
#pragma unroll 1
            for (int li = wid; li < nflag; li += 8) {
                int rowl = sLst[li];
                float thr = sBest[rowl] - TAU;
                float wb = -3.4e38f, wb2 = -3.4e38f; int wic = 0;
                if (lane < 8) {
                    float2 v = sR2[rowl * 8 + lane];
                    wb = v.x; wb2 = v.y;
                    wic = sRI[rowl * 8 + lane];
                }
                unsigned candm  = __ballot_sync(0xffffffffu, wb  >= thr);
                unsigned heavym = __ballot_sync(0xffffffffu, wb  >= thr && wb2 >= thr);
                unsigned lightm = candm & ~heavym;

                float4 f[16];
                {
                    const float4* zr = (const float4*)(smem + zoff + rowl * 256);
#pragma unroll
                    for (int i = 0; i < 16; i++) f[i] = zr[i];
                }
                float lb = -3.4e38f; int lj = NC;
                if (lightm & (1u << lane)) {
                    lb = exact_score(f, emb, sH, wic);
                    lj = wic;
                }
#pragma unroll 1
                while (heavym) {       // heavy block = 64 codes -> 2 scans
                    int c = __ffs(heavym) - 1; heavym &= heavym - 1;
#pragma unroll
                    for (int s = 0; s < 2; s++) {
                        int j = 64 * c + 32 * s + lane;
                        float sc = exact_score(f, emb, sH, j);
                        if (sc > lb || (sc == lb && j < lj)) { lb = sc; lj = j; }
                    }
                }
#pragma unroll
                for (int m = 16; m; m >>= 1) {
                    float ob = __shfl_xor_sync(0xffffffffu, lb, m);
                    int   oj = __shfl_xor_sync(0xffffffffu, lj, m);
                    if (ob > lb || (ob == lb && oj < lj)) { lb = ob; lj = oj; }
                }
                if (lane == 0) sBI[rowl] = lj;
            }
            __syncthreads();
        }

        // ---- epilogue: thread -> row tid/4, quarter tid%4 (z from smem) ----
        {
            int bi = sBI[myrow];
            size_t rg = (size_t)tile * TROWS + myrow;
            if (myq == 0) {
                out[O_IDX + rg] = (float)bi;
                atomicAdd(&sCnt[bi], 1.0f);
            }
            const float4* er = (const float4*)(emb + (size_t)bi * CD + myq * 16);
            const float4* zr = (const float4*)(smem + zoff + myrow * 256 + myq * 64);
            float4* oq = (float4*)(out + O_ZQ + rg * CD + myq * 16);
            float* es = g_esum + (size_t)bi * CD + myq * 16;
#pragma unroll
            for (int i = 0; i < 4; i++) {
                float4 e = er[i], zf = zr[i];
                float d0 = e.x - zf.x, d1 = e.y - zf.y;
                float d2 = e.z - zf.z, d3 = e.w - zf.w;
                sse_acc += d0 * d0 + d1 * d1 + d2 * d2 + d3 * d3;
                oq[i] = make_float4(zf.x + d0, zf.y + d1, zf.z + d2, zf.w + d3);
                asm volatile("red.global.add.v4.f32 [%0], {%1,%2,%3,%4};"
                    :: "l"(es + i * 4), "f"(zf.x), "f"(zf.y), "f"(zf.z), "f"(zf.w)
                    : "memory");
            }
        }
    }

    // ---- final merges ----
    __syncthreads();
#pragma unroll
    for (int i = 0; i < 2; i++) {
        float c = sCnt[tid + 256 * i];
        if (c != 0.0f) atomicAdd(&g_counts[tid + 256 * i], c);
    }
#pragma unroll
    for (int m = 16; m; m >>= 1) sse_acc += __shfl_xor_sync(0xffffffffu, sse_acc, m);
    if (lane == 0 && sse_acc != 0.0f) atomicAdd(&g_sse, sse_acc);
}

// ============================================================================
// Kernel 3: finalize EMA + loss
// ============================================================================
__global__ void vq_final(const float* __restrict__ cluster_size,
                         const float* __restrict__ embedding_avg,
                         float* __restrict__ out) {
    __shared__ float red[NC];
    const int j = threadIdx.x;
    float cnt = g_counts[j];
    float ncs = cluster_size[j] * 0.99f + 0.01f * cnt;
    out[O_NCS + j] = ncs;
    red[j] = ncs;
    __syncthreads();
#pragma unroll
    for (int o = NC / 2; o > 0; o >>= 1) {
        if (j < o) red[j] += red[j + o];
        __syncthreads();
    }
    float n  = red[0];
    float cs = (ncs + 1e-6f) / (n + (float)NC * 1e-6f);
#pragma unroll 4
    for (int k = 0; k < CD; k++) {
        float ea = embedding_avg[(size_t)j * CD + k] * 0.99f
                 + 0.01f * g_esum[(size_t)j * CD + k];
        out[O_NAVG + (size_t)j * CD + k] = ea;
        out[O_NEMB + (size_t)j * CD + k] = ea / cs;
    }
    if (j == 0) out[O_LOSS] = 0.25f * g_sse / (float)NELEM;
}

// ============================================================================
extern "C" void kernel_launch(void* const* d_in, const int* in_sizes, int n_in,
                              void* d_out, int out_size) {
    const float* z    = (const float*)d_in[0];
    const float* emb  = (const float*)d_in[1];
    const float* csz  = (const float*)d_in[2];
    const float* eavg = (const float*)d_in[3];
    float* out = (float*)d_out;

    cudaFuncSetAttribute(vq_main, cudaFuncAttributeMaxDynamicSharedMemorySize, SMEM_SZ);
    vq_init<<<64, 512>>>(emb);
    vq_nop1<<<1, 1>>>();
    vq_nop2<<<1, 1>>>();
    vq_main<<<GRID, 256, SMEM_SZ>>>(z, emb, out);
    vq_final<<<1, NC>>>(csz, eavg, out);
}

// round 10
// speedup vs baseline: 2.6253x; 1.3136x over previous
#include <cuda_runtime.h>
#include <cuda_fp16.h>
#include <cstdint>

// ============================================================================
// VectorQuantizerEMA — persistent 2-CTA/SM HMMA, single-pass fp16 scoring,
// candidate-pruned exact fp32 recheck, overlapped epilogue, parallel finalize.
// ============================================================================

#define NC      512
#define CD      64
#define NROWS   (64 * 4096)
#define NELEM   (NROWS * CD)
#define TROWS   64
#define NTILES  (NROWS / TROWS)     // 4096
#define GRID    296                 // 2 CTAs per SM
#define TAU     0.15f

#define O_ZQ    ((size_t)0)
#define O_LOSS  ((size_t)16777216)
#define O_IDX   ((size_t)16777217)
#define O_NEMB  ((size_t)17039361)
#define O_NCS   ((size_t)17072129)
#define O_NAVG  ((size_t)17072641)

// ---- device scratch --------------------------------------------------------
__device__ __align__(16) float g_esum[NC * CD];
__device__ __align__(16) unsigned short g_Bh16[NC * CD];  // fp16 E row-major
__device__ float g_counts[NC];
__device__ float g_h[NC];            // 0.5*||e||^2
__device__ float g_sse;

// ---- smem layout (bytes, per CTA) ------------------------------------------
#define SM_Z0    0        // 16KB raw z tile buf A
#define SM_Z1    16384    // 16KB raw z tile buf B
#define SM_AH    32768    // 8KB fp16 A, swizzled
#define SM_R2    40960    // 4KB float2 (best,best2) per (row,warp)  64x8
#define SM_RI    45056    // 1KB u16 idx per (row,warp)
#define SM_H     46080    // 2KB
#define SM_CNT   48128    // 2KB
#define SM_BI    50176    // 256B
#define SM_BEST  50432    // 256B
#define SM_LIST  50688    // 256B
#define SM_FLG   50944    // 64B  per-row flag
#define SM_NFLG  51008
#define SMEM_SZ  51072

__device__ __forceinline__ uint32_t smem_u32(const void* p) {
    uint32_t a;
    asm("{ .reg .u64 t; cvta.to.shared.u64 t, %1; cvt.u32.u64 %0, t; }" : "=r"(a) : "l"(p));
    return a;
}
__device__ __forceinline__ void ldsm_x4(uint32_t a, uint32_t* r) {
    asm volatile("ldmatrix.sync.aligned.m8n8.x4.shared.b16 {%0,%1,%2,%3}, [%4];"
        : "=r"(r[0]), "=r"(r[1]), "=r"(r[2]), "=r"(r[3]) : "r"(a));
}
__device__ __forceinline__ void mma16816(float* c, const uint32_t* a, const uint32_t* b) {
    asm volatile("mma.sync.aligned.m16n8k16.row.col.f32.f16.f16.f32 "
        "{%0,%1,%2,%3}, {%4,%5,%6,%7}, {%8,%9}, {%0,%1,%2,%3};"
        : "+f"(c[0]), "+f"(c[1]), "+f"(c[2]), "+f"(c[3])
        : "r"(a[0]), "r"(a[1]), "r"(a[2]), "r"(a[3]), "r"(b[0]), "r"(b[1]));
}
__device__ __forceinline__ uint32_t packh(float x, float y) {
    __half2 h = __floats2half2_rn(x, y);
    return *(uint32_t*)&h;
}
__device__ __forceinline__ void cp16(uint32_t d, const void* s) {
    asm volatile("cp.async.cg.shared.global [%0], [%1], 16;" :: "r"(d), "l"(s));
}
#define CP_COMMIT() asm volatile("cp.async.commit_group;")
#define CP_WAIT0()  asm volatile("cp.async.wait_group 0;")

__device__ __forceinline__ float exact_score(const float4* __restrict__ f,
                                             const float* __restrict__ emb,
                                             const float* __restrict__ sH, int j) {
    const float4* er = (const float4*)(emb + (size_t)j * CD);
    float acc = 0.0f;
#pragma unroll
    for (int i = 0; i < 16; i++) {
        float4 e = er[i];
        acc += f[i].x * e.x + f[i].y * e.y + f[i].z * e.z + f[i].w * e.w;
    }
    return acc - sH[j];
}

// ============================================================================
// Kernel 1: zero scratch, half-norms, fp16 B
// ============================================================================
__global__ void vq_init(const float* __restrict__ emb) {
    int t = blockIdx.x * blockDim.x + threadIdx.x;   // 32768
    if (t < NC * CD) {
        g_esum[t] = 0.0f;
        g_Bh16[t] = __half_as_ushort(__float2half_rn(emb[t]));
    }
    if (t == 0) g_sse = 0.0f;
    if (t < NC) {
        g_counts[t] = 0.0f;
        const float4* e = (const float4*)(emb + (size_t)t * CD);
        float s = 0.0f;
#pragma unroll
        for (int i = 0; i < CD / 4; i++) {
            float4 v = e[i];
            s += v.x * v.x + v.y * v.y + v.z * v.z + v.w * v.w;
        }
        g_h[t] = 0.5f * s;
    }
}

// no-op spacers so ncu -s 5 lands on vq_main
__global__ void vq_nop1() {}
__global__ void vq_nop2() {}

// ============================================================================
// Kernel 2: persistent main. 296 CTAs x 256 thr (8 warps), 64-row tiles.
// ============================================================================
__global__ void __launch_bounds__(256, 2)
vq_main(const float* __restrict__ z, const float* __restrict__ emb,
        float* __restrict__ out) {
    extern __shared__ __align__(16) char smem[];
    const uint32_t sb32 = smem_u32(smem);
    float*  sH   = (float*)(smem + SM_H);
    float*  sCnt = (float*)(smem + SM_CNT);
    int*    sBI  = (int*)(smem + SM_BI);
    float*  sBest= (float*)(smem + SM_BEST);
    int*    sLst = (int*)(smem + SM_LIST);
    unsigned char* sFlg = (unsigned char*)(smem + SM_FLG);
    int*    sNF  = (int*)(smem + SM_NFLG);
    float2* sR2  = (float2*)(smem + SM_R2);
    unsigned short* sRI = (unsigned short*)(smem + SM_RI);

    const int tid  = threadIdx.x;
    const int wid  = tid >> 5;      // 0..7
    const int lane = tid & 31;

    // ---- prologue: prefetch first tile; stage h; zero counters ----
    {
        uint32_t dst = sb32 + SM_Z0;
        const char* src = (const char*)(z + (size_t)blockIdx.x * TROWS * CD);
#pragma unroll
        for (int i = 0; i < 4; i++) {
            int c = tid + i * 256;
            cp16(dst + c * 16, src + c * 16);
        }
        CP_COMMIT();
    }
#pragma unroll
    for (int i = 0; i < 2; i++) {
        sH[tid + 256 * i] = g_h[tid + 256 * i];
        sCnt[tid + 256 * i] = 0.0f;
    }

    const int jw = wid * 64;
    // ---- hoist B fragments once: 8 nt x 4 ks x {b0,b1} = 64 regs ----
    uint32_t Breg[8][4][2];
#pragma unroll
    for (int nt = 0; nt < 8; nt++) {
        int code = jw + nt * 8 + (lane >> 2);
        const uint32_t* row = (const uint32_t*)(g_Bh16 + (size_t)code * CD);
#pragma unroll
        for (int ks = 0; ks < 4; ks++) {
            int k2 = ks * 8 + (lane & 3);
            Breg[nt][ks][0] = row[k2];
            Breg[nt][ks][1] = row[k2 + 4];
        }
    }
    __syncthreads();

    // per-lane half-norms for the 16 (h,n4,u) slots
    float hreg[16];
#pragma unroll
    for (int h = 0; h < 2; h++)
#pragma unroll
        for (int n4 = 0; n4 < 4; n4++)
#pragma unroll
            for (int u = 0; u < 2; u++)
                hreg[h * 8 + n4 * 2 + u] =
                    sH[jw + h * 32 + n4 * 8 + 2 * (lane & 3) + u];

    const int myrow = tid >> 2;          // 0..63
    const int myq   = tid & 3;

    float sse_acc = 0.0f;
    int it = 0;
#pragma unroll 1
    for (int tile = blockIdx.x; tile < NTILES; tile += GRID, it++) {
        const uint32_t zoff = (it & 1) ? SM_Z1 : SM_Z0;

        CP_WAIT0();
        __syncthreads();                 // cur z resident; prev phases done

        // ---- convert: z quarter -> fp16 AH (swizzled) ----
        {
            const float4* zr = (const float4*)(smem + zoff + myrow * 256 + myq * 64);
            float4 v0 = zr[0], v1 = zr[1], v2 = zr[2], v3 = zr[3];
            uint4 H0, H1;
            H0.x = packh(v0.x, v0.y); H0.y = packh(v0.z, v0.w);
            H0.z = packh(v1.x, v1.y); H0.w = packh(v1.z, v1.w);
            H1.x = packh(v2.x, v2.y); H1.y = packh(v2.z, v2.w);
            H1.z = packh(v3.x, v3.y); H1.w = packh(v3.z, v3.w);
            uint4* pH = (uint4*)(smem + SM_AH + myrow * 128);
            pH[(2 * myq) ^ (myrow & 7)]     = H0;
            pH[(2 * myq + 1) ^ (myrow & 7)] = H1;
        }
        if (tid == 0) *sNF = 0;
        __syncthreads();

        // ---- prefetch next tile into other buffer (overlaps MMA) ----
        {
            int tn = tile + GRID;
            if (tn < NTILES) {
                uint32_t dst = sb32 + ((it & 1) ? SM_Z0 : SM_Z1);
                const char* src = (const char*)(z + (size_t)tn * TROWS * CD);
#pragma unroll
                for (int i = 0; i < 4; i++) {
                    int c = tid + i * 256;
                    cp16(dst + c * 16, src + c * 16);
                }
            }
            CP_COMMIT();
        }

        // ---- MMA mainloop: 4 row-tiles x two 4-nt halves ----
#pragma unroll 1
        for (int rt = 0; rt < 4; rt++) {
            uint32_t Ah[16];
            {
                int rl = 16 * rt + (lane & 7) + (((lane >> 3) & 1) << 3);
                int ch = (lane >> 4) & 1;
                uint32_t baseH = sb32 + SM_AH + rl * 128;
                int sw = rl & 7;
#pragma unroll
                for (int ks = 0; ks < 4; ks++)
                    ldsm_x4(baseH + (((2 * ks + ch) ^ sw) << 4), &Ah[ks * 4]);
            }
            float b1a = -3.4e38f, b2a = -3.4e38f; int i1a = 0;
            float b1b = -3.4e38f, b2b = -3.4e38f; int i1b = 0;
#pragma unroll
            for (int h = 0; h < 2; h++) {
                float C[16];
#pragma unroll
                for (int i = 0; i < 16; i++) C[i] = 0.0f;
#pragma unroll
                for (int n4 = 0; n4 < 4; n4++)
#pragma unroll
                    for (int ks = 0; ks < 4; ks++)
                        mma16816(&C[n4 * 4], &Ah[ks * 4], Breg[h * 4 + n4][ks]);

#pragma unroll
                for (int n4 = 0; n4 < 4; n4++) {
#pragma unroll
                    for (int u = 0; u < 2; u++) {
                        int j = jw + h * 32 + n4 * 8 + 2 * (lane & 3) + u;
                        float hh = hreg[h * 8 + n4 * 2 + u];
                        float s = C[n4 * 4 + u] - hh;
                        if (s > b1a) { b2a = b1a; b1a = s; i1a = j; }
                        else if (s > b2a) b2a = s;
                        float s2 = C[n4 * 4 + 2 + u] - hh;
                        if (s2 > b1b) { b2b = b1b; b1b = s2; i1b = j; }
                        else if (s2 > b2b) b2b = s2;
                    }
                }
            }
#pragma unroll
            for (int m = 1; m <= 2; m <<= 1) {
                float ob  = __shfl_xor_sync(0xffffffffu, b1a, m);
                float ob2 = __shfl_xor_sync(0xffffffffu, b2a, m);
                int   oi  = __shfl_xor_sync(0xffffffffu, i1a, m);
                bool take = (ob > b1a) || (ob == b1a && oi < i1a);
                float loser = take ? b1a : ob;
                b2a = fmaxf(fmaxf(b2a, ob2), loser);
                if (take) { b1a = ob; i1a = oi; }
                ob  = __shfl_xor_sync(0xffffffffu, b1b, m);
                ob2 = __shfl_xor_sync(0xffffffffu, b2b, m);
                oi  = __shfl_xor_sync(0xffffffffu, i1b, m);
                take = (ob > b1b) || (ob == b1b && oi < i1b);
                loser = take ? b1b : ob;
                b2b = fmaxf(fmaxf(b2b, ob2), loser);
                if (take) { b1b = ob; i1b = oi; }
            }
            if ((lane & 3) == 0) {
                int g = lane >> 2;
                int r0 = 16 * rt + g, r1 = r0 + 8;
                sR2[r0 * 8 + wid] = make_float2(b1a, b2a);
                sRI[r0 * 8 + wid] = (unsigned short)i1a;
                sR2[r1 * 8 + wid] = make_float2(b1b, b2b);
                sRI[r1 * 8 + wid] = (unsigned short)i1b;
            }
        }
        __syncthreads();

        // ---- per-row combine: 2 threads/row (warps 0-3), then 1 shfl ----
        if (tid < 128) {
            int row = tid >> 1, half = tid & 1;
            float b = -3.4e38f, b2 = -3.4e38f; int bi = 0;
#pragma unroll
            for (int w = 0; w < 4; w++) {
                int wi = half * 4 + w;
                float2 v = sR2[row * 8 + wi];
                int oi = sRI[row * 8 + wi];
                bool take = (v.x > b) || (v.x == b && oi < bi);
                float loser = take ? b : v.x;
                b2 = fmaxf(fmaxf(b2, v.y), loser);
                if (take) { b = v.x; bi = oi; }
            }
            float ob  = __shfl_xor_sync(0xffffffffu, b, 1);
            float ob2 = __shfl_xor_sync(0xffffffffu, b2, 1);
            int   oi  = __shfl_xor_sync(0xffffffffu, bi, 1);
            bool take = (ob > b) || (ob == b && oi < bi);
            float loser = take ? b : ob;
            b2 = fmaxf(fmaxf(b2, ob2), loser);
            if (take) { b = ob; bi = oi; }
            if (half == 0) {
                sBI[row] = bi;
                sBest[row] = b;
                int flag = (b - b2 < TAU) ? 1 : 0;
                sFlg[row] = (unsigned char)flag;
                if (flag) {
                    int p = atomicAdd(sNF, 1);
                    sLst[p] = row;
                }
            }
        }
        __syncthreads();
        const int nflag = *sNF;
        const bool mine_flagged = sFlg[myrow] != 0;

        // ---- epilogue helper (z from smem zoff) ----
        auto do_epilogue = [&](int bi) {
            size_t rg = (size_t)tile * TROWS + myrow;
            if (myq == 0) {
                out[O_IDX + rg] = (float)bi;
                atomicAdd(&sCnt[bi], 1.0f);
            }
            const float4* er = (const float4*)(emb + (size_t)bi * CD + myq * 16);
            const float4* zr = (const float4*)(smem + zoff + myrow * 256 + myq * 64);
            float4* oq = (float4*)(out + O_ZQ + rg * CD + myq * 16);
            float* es = g_esum + (size_t)bi * CD + myq * 16;
#pragma unroll
            for (int i = 0; i < 4; i++) {
                float4 e = er[i], zf = zr[i];
                float d0 = e.x - zf.x, d1 = e.y - zf.y;
                float d2 = e.z - zf.z, d3 = e.w - zf.w;
                sse_acc += d0 * d0 + d1 * d1 + d2 * d2 + d3 * d3;
                oq[i] = make_float4(zf.x + d0, zf.y + d1, zf.z + d2, zf.w + d3);
                asm volatile("red.global.add.v4.f32 [%0], {%1,%2,%3,%4};"
                    :: "l"(es + i * 4), "f"(zf.x), "f"(zf.y), "f"(zf.z), "f"(zf.w)
                    : "memory");
            }
        };

        // ---- epilogue for unflagged rows (overlaps recheck below) ----
        if (!mine_flagged) do_epilogue(sBI[myrow]);

        // ---- candidate-pruned exact recheck for flagged rows ----
        if (nflag > 0) {
#pragma unroll 1
            for (int li = wid; li < nflag; li += 8) {
                int rowl = sLst[li];
                float thr = sBest[rowl] - TAU;
                float wb = -3.4e38f, wb2 = -3.4e38f; int wic = 0;
                if (lane < 8) {
                    float2 v = sR2[rowl * 8 + lane];
                    wb = v.x; wb2 = v.y;
                    wic = sRI[rowl * 8 + lane];
                }
                unsigned candm  = __ballot_sync(0xffffffffu, wb  >= thr);
                unsigned heavym = __ballot_sync(0xffffffffu, wb  >= thr && wb2 >= thr);
                unsigned lightm = candm & ~heavym;

                float4 f[16];
                {
                    const float4* zr = (const float4*)(smem + zoff + rowl * 256);
#pragma unroll
                    for (int i = 0; i < 16; i++) f[i] = zr[i];
                }
                float lb = -3.4e38f; int lj = NC;
                if (lightm & (1u << lane)) {
                    lb = exact_score(f, emb, sH, wic);
                    lj = wic;
                }
#pragma unroll 1
                while (heavym) {       // heavy block = 64 codes -> 2 scans
                    int c = __ffs(heavym) - 1; heavym &= heavym - 1;
#pragma unroll
                    for (int s = 0; s < 2; s++) {
                        int j = 64 * c + 32 * s + lane;
                        float sc = exact_score(f, emb, sH, j);
                        if (sc > lb || (sc == lb && j < lj)) { lb = sc; lj = j; }
                    }
                }
#pragma unroll
                for (int m = 16; m; m >>= 1) {
                    float ob = __shfl_xor_sync(0xffffffffu, lb, m);
                    int   oj = __shfl_xor_sync(0xffffffffu, lj, m);
                    if (ob > lb || (ob == lb && oj < lj)) { lb = ob; lj = oj; }
                }
                if (lane == 0) sBI[rowl] = lj;
            }
            __syncthreads();
            // ---- deferred epilogue for flagged rows ----
            if (mine_flagged) do_epilogue(sBI[myrow]);
        }
    }

    // ---- final merges ----
    __syncthreads();
#pragma unroll
    for (int i = 0; i < 2; i++) {
        float c = sCnt[tid + 256 * i];
        if (c != 0.0f) atomicAdd(&g_counts[tid + 256 * i], c);
    }
#pragma unroll
    for (int m = 16; m; m >>= 1) sse_acc += __shfl_xor_sync(0xffffffffu, sse_acc, m);
    if (lane == 0 && sse_acc != 0.0f) atomicAdd(&g_sse, sse_acc);
}

// ============================================================================
// Kernel 3: finalize EMA + loss. 64 blocks x 512 thr; each block redundantly
// computes the (deterministic) cluster-size sum, then handles 8 codes.
// ============================================================================
__global__ void vq_final(const float* __restrict__ cluster_size,
                         const float* __restrict__ embedding_avg,
                         float* __restrict__ out) {
    __shared__ float sncs[NC];
    __shared__ float sred[NC];
    const int t = threadIdx.x;       // 0..511
    const int b = blockIdx.x;        // 0..63

    float ncs = cluster_size[t] * 0.99f + 0.01f * g_counts[t];
    sncs[t] = ncs;
    sred[t] = ncs;
    if (b == 0) out[O_NCS + t] = ncs;
    __syncthreads();
#pragma unroll
    for (int o = NC / 2; o > 0; o >>= 1) {
        if (t < o) sred[t] += sred[t + o];
        __syncthreads();
    }
    const float n = sred[0];

    const int code = 8 * b + (t >> 6);
    const int k = t & 63;
    const size_t o = (size_t)code * CD + k;
    float ea = embedding_avg[o] * 0.99f + 0.01f * g_esum[o];
    out[O_NAVG + o] = ea;
    float cs = (sncs[code] + 1e-6f) / (n + (float)NC * 1e-6f);
    out[O_NEMB + o] = ea / cs;

    if (b == 0 && t == 0) out[O_LOSS] = 0.25f * g_sse / (float)NELEM;
}

// ============================================================================
extern "C" void kernel_launch(void* const* d_in, const int* in_sizes, int n_in,
                              void* d_out, int out_size) {
    const float* z    = (const float*)d_in[0];
    const float* emb  = (const float*)d_in[1];
    const float* csz  = (const float*)d_in[2];
    const float* eavg = (const float*)d_in[3];
    float* out = (float*)d_out;

    cudaFuncSetAttribute(vq_main, cudaFuncAttributeMaxDynamicSharedMemorySize, SMEM_SZ);
    vq_init<<<64, 512>>>(emb);
    vq_nop1<<<1, 1>>>();
    vq_nop2<<<1, 1>>>();
    vq_main<<<GRID, 256, SMEM_SZ>>>(z, emb, out);
    vq_final<<<64, NC>>>(csz, eavg, out);
}

// round 11
// speedup vs baseline: 2.6508x; 1.0097x over previous
#include <cuda_runtime.h>
#include <cuda_fp16.h>
#include <cstdint>

// ============================================================================
// VectorQuantizerEMA — persistent 2-CTA/SM HMMA, single-pass fp16 scoring,
// packed-key tournament argmax, candidate-pruned exact fp32 recheck.
// ============================================================================

#define NC      512
#define CD      64
#define NROWS   (64 * 4096)
#define NELEM   (NROWS * CD)
#define TROWS   64
#define NTILES  (NROWS / TROWS)     // 4096
#define GRID    296                 // 2 CTAs per SM
#define TAU     0.15f

#define O_ZQ    ((size_t)0)
#define O_LOSS  ((size_t)16777216)
#define O_IDX   ((size_t)16777217)
#define O_NEMB  ((size_t)17039361)
#define O_NCS   ((size_t)17072129)
#define O_NAVG  ((size_t)17072641)

// ---- device scratch --------------------------------------------------------
__device__ __align__(16) float g_esum[NC * CD];
__device__ __align__(16) unsigned short g_Bh16[NC * CD];  // fp16 E row-major
__device__ float g_counts[NC];
__device__ float g_h[NC];            // 0.5*||e||^2
__device__ float g_sse;

// ---- smem layout (bytes, per CTA) ------------------------------------------
#define SM_Z0    0        // 16KB raw z tile buf A
#define SM_Z1    16384    // 16KB raw z tile buf B
#define SM_AH    32768    // 8KB fp16 A, swizzled
#define SM_R2    40960    // 4KB uint2 (key1,key2) per (row,warp)  64x8
#define SM_H     45056    // 2KB
#define SM_CNT   47104    // 2KB
#define SM_BI    49152    // 256B
#define SM_BEST  49408    // 256B
#define SM_LIST  49664    // 256B
#define SM_FLG   49920    // 64B
#define SM_NFLG  49984
#define SMEM_SZ  50048

__device__ __forceinline__ uint32_t smem_u32(const void* p) {
    uint32_t a;
    asm("{ .reg .u64 t; cvta.to.shared.u64 t, %1; cvt.u32.u64 %0, t; }" : "=r"(a) : "l"(p));
    return a;
}
__device__ __forceinline__ void ldsm_x4(uint32_t a, uint32_t* r) {
    asm volatile("ldmatrix.sync.aligned.m8n8.x4.shared.b16 {%0,%1,%2,%3}, [%4];"
        : "=r"(r[0]), "=r"(r[1]), "=r"(r[2]), "=r"(r[3]) : "r"(a));
}
__device__ __forceinline__ void mma16816(float* c, const uint32_t* a, const uint32_t* b) {
    asm volatile("mma.sync.aligned.m16n8k16.row.col.f32.f16.f16.f32 "
        "{%0,%1,%2,%3}, {%4,%5,%6,%7}, {%8,%9}, {%0,%1,%2,%3};"
        : "+f"(c[0]), "+f"(c[1]), "+f"(c[2]), "+f"(c[3])
        : "r"(a[0]), "r"(a[1]), "r"(a[2]), "r"(a[3]), "r"(b[0]), "r"(b[1]));
}
__device__ __forceinline__ uint32_t packh(float x, float y) {
    __half2 h = __floats2half2_rn(x, y);
    return *(uint32_t*)&h;
}
__device__ __forceinline__ void cp16(uint32_t d, const void* s) {
    asm volatile("cp.async.cg.shared.global [%0], [%1], 16;" :: "r"(d), "l"(s));
}
#define CP_COMMIT() asm volatile("cp.async.commit_group;")
#define CP_WAIT0()  asm volatile("cp.async.wait_group 0;")

// ---- packed monotonic keys -------------------------------------------------
// key = (monotonic(score) & ~0x1FF) | (511 - j). Unsigned key order == score
// order (quantized to 14 mantissa bits, step <= ~0.004 here); ties -> lowest j.
__device__ __forceinline__ uint32_t mkkey(float s, int j) {
    uint32_t u = __float_as_uint(s);
    u ^= (uint32_t)((int32_t)u >> 31) | 0x80000000u;
    return (u & 0xFFFFFE00u) | (uint32_t)(511 - j);
}
__device__ __forceinline__ float dkey(uint32_t k) {
    uint32_t u = k & 0xFFFFFE00u;
    u = (u & 0x80000000u) ? (u ^ 0x80000000u) : ~u;
    return __uint_as_float(u);
}
__device__ __forceinline__ uint32_t umaxu(uint32_t a, uint32_t b) { return a > b ? a : b; }
__device__ __forceinline__ uint32_t uminu(uint32_t a, uint32_t b) { return a < b ? a : b; }
// merge (m1,m2) with (o1,o2): exact top-2 of union
__device__ __forceinline__ void pmerge(uint32_t& m1, uint32_t& m2,
                                       uint32_t o1, uint32_t o2) {
    m2 = umaxu(umaxu(m2, o2), uminu(m1, o1));
    m1 = umaxu(m1, o1);
}
// exact top-2 of 8 keys (tournament, depth ~4, full ILP)
__device__ __forceinline__ void top2of8(const uint32_t* k, uint32_t& m1, uint32_t& m2) {
    uint32_t x1[4], x2[4];
#pragma unroll
    for (int i = 0; i < 4; i++) {
        x1[i] = umaxu(k[2 * i], k[2 * i + 1]);
        x2[i] = uminu(k[2 * i], k[2 * i + 1]);
    }
    uint32_t y1a = umaxu(x1[0], x1[1]);
    uint32_t y2a = umaxu(uminu(x1[0], x1[1]), umaxu(x2[0], x2[1]));
    uint32_t y1b = umaxu(x1[2], x1[3]);
    uint32_t y2b = umaxu(uminu(x1[2], x1[3]), umaxu(x2[2], x2[3]));
    m1 = umaxu(y1a, y1b);
    m2 = umaxu(uminu(y1a, y1b), umaxu(y2a, y2b));
}

__device__ __forceinline__ float exact_score(const float4* __restrict__ f,
                                             const float* __restrict__ emb,
                                             const float* __restrict__ sH, int j) {
    const float4* er = (const float4*)(emb + (size_t)j * CD);
    float acc = 0.0f;
#pragma unroll
    for (int i = 0; i < 16; i++) {
        float4 e = er[i];
        acc += f[i].x * e.x + f[i].y * e.y + f[i].z * e.z + f[i].w * e.w;
    }
    return acc - sH[j];
}

// ============================================================================
// Kernel 1: zero scratch, half-norms, fp16 B
// ============================================================================
__global__ void vq_init(const float* __restrict__ emb) {
    int t = blockIdx.x * blockDim.x + threadIdx.x;   // 32768
    if (t < NC * CD) {
        g_esum[t] = 0.0f;
        g_Bh16[t] = __half_as_ushort(__float2half_rn(emb[t]));
    }
    if (t == 0) g_sse = 0.0f;
    if (t < NC) {
        g_counts[t] = 0.0f;
        const float4* e = (const float4*)(emb + (size_t)t * CD);
        float s = 0.0f;
#pragma unroll
        for (int i = 0; i < CD / 4; i++) {
            float4 v = e[i];
            s += v.x * v.x + v.y * v.y + v.z * v.z + v.w * v.w;
        }
        g_h[t] = 0.5f * s;
    }
}

// no-op spacers so ncu -s 5 lands on vq_main
__global__ void vq_nop1() {}
__global__ void vq_nop2() {}

// ============================================================================
// Kernel 2: persistent main. 296 CTAs x 256 thr (8 warps), 64-row tiles.
// ============================================================================
__global__ void __launch_bounds__(256, 2)
vq_main(const float* __restrict__ z, const float* __restrict__ emb,
        float* __restrict__ out) {
    extern __shared__ __align__(16) char smem[];
    const uint32_t sb32 = smem_u32(smem);
    float*  sH   = (float*)(smem + SM_H);
    float*  sCnt = (float*)(smem + SM_CNT);
    int*    sBI  = (int*)(smem + SM_BI);
    float*  sBest= (float*)(smem + SM_BEST);
    int*    sLst = (int*)(smem + SM_LIST);
    unsigned char* sFlg = (unsigned char*)(smem + SM_FLG);
    int*    sNF  = (int*)(smem + SM_NFLG);
    uint2*  sR2  = (uint2*)(smem + SM_R2);

    const int tid  = threadIdx.x;
    const int wid  = tid >> 5;      // 0..7
    const int lane = tid & 31;

    // ---- prologue: prefetch first tile; stage h; zero counters ----
    {
        uint32_t dst = sb32 + SM_Z0;
        const char* src = (const char*)(z + (size_t)blockIdx.x * TROWS * CD);
#pragma unroll
        for (int i = 0; i < 4; i++) {
            int c = tid + i * 256;
            cp16(dst + c * 16, src + c * 16);
        }
        CP_COMMIT();
    }
#pragma unroll
    for (int i = 0; i < 2; i++) {
        sH[tid + 256 * i] = g_h[tid + 256 * i];
        sCnt[tid + 256 * i] = 0.0f;
    }

    const int jw = wid * 64;
    // ---- hoist B fragments once: 8 nt x 4 ks x {b0,b1} = 64 regs ----
    uint32_t Breg[8][4][2];
#pragma unroll
    for (int nt = 0; nt < 8; nt++) {
        int code = jw + nt * 8 + (lane >> 2);
        const uint32_t* row = (const uint32_t*)(g_Bh16 + (size_t)code * CD);
#pragma unroll
        for (int ks = 0; ks < 4; ks++) {
            int k2 = ks * 8 + (lane & 3);
            Breg[nt][ks][0] = row[k2];
            Breg[nt][ks][1] = row[k2 + 4];
        }
    }
    __syncthreads();

    // per-lane half-norms for the 16 (h,n4,u) slots
    float hreg[16];
#pragma unroll
    for (int h = 0; h < 2; h++)
#pragma unroll
        for (int n4 = 0; n4 < 4; n4++)
#pragma unroll
            for (int u = 0; u < 2; u++)
                hreg[h * 8 + n4 * 2 + u] =
                    sH[jw + h * 32 + n4 * 8 + 2 * (lane & 3) + u];

    const int myrow = tid >> 2;          // 0..63
    const int myq   = tid & 3;

    float sse_acc = 0.0f;
    int it = 0;
#pragma unroll 1
    for (int tile = blockIdx.x; tile < NTILES; tile += GRID, it++) {
        const uint32_t zoff = (it & 1) ? SM_Z1 : SM_Z0;

        CP_WAIT0();
        __syncthreads();                 // cur z resident; prev phases done

        // ---- convert: z quarter -> fp16 AH (swizzled) ----
        {
            const float4* zr = (const float4*)(smem + zoff + myrow * 256 + myq * 64);
            float4 v0 = zr[0], v1 = zr[1], v2 = zr[2], v3 = zr[3];
            uint4 H0, H1;
            H0.x = packh(v0.x, v0.y); H0.y = packh(v0.z, v0.w);
            H0.z = packh(v1.x, v1.y); H0.w = packh(v1.z, v1.w);
            H1.x = packh(v2.x, v2.y); H1.y = packh(v2.z, v2.w);
            H1.z = packh(v3.x, v3.y); H1.w = packh(v3.z, v3.w);
            uint4* pH = (uint4*)(smem + SM_AH + myrow * 128);
            pH[(2 * myq) ^ (myrow & 7)]     = H0;
            pH[(2 * myq + 1) ^ (myrow & 7)] = H1;
        }
        if (tid == 0) *sNF = 0;
        __syncthreads();

        // ---- prefetch next tile into other buffer (overlaps MMA) ----
        {
            int tn = tile + GRID;
            if (tn < NTILES) {
                uint32_t dst = sb32 + ((it & 1) ? SM_Z0 : SM_Z1);
                const char* src = (const char*)(z + (size_t)tn * TROWS * CD);
#pragma unroll
                for (int i = 0; i < 4; i++) {
                    int c = tid + i * 256;
                    cp16(dst + c * 16, src + c * 16);
                }
            }
            CP_COMMIT();
        }

        // ---- MMA mainloop: 4 row-tiles x two 4-nt halves; key extraction ----
#pragma unroll 1
        for (int rt = 0; rt < 4; rt++) {
            uint32_t Ah[16];
            {
                int rl = 16 * rt + (lane & 7) + (((lane >> 3) & 1) << 3);
                int ch = (lane >> 4) & 1;
                uint32_t baseH = sb32 + SM_AH + rl * 128;
                int sw = rl & 7;
#pragma unroll
                for (int ks = 0; ks < 4; ks++)
                    ldsm_x4(baseH + (((2 * ks + ch) ^ sw) << 4), &Ah[ks * 4]);
            }
            uint32_t a1, a2, b1, b2;     // running top-2 keys, rows a & b
#pragma unroll
            for (int h = 0; h < 2; h++) {
                float C[16];
#pragma unroll
                for (int i = 0; i < 16; i++) C[i] = 0.0f;
#pragma unroll
                for (int n4 = 0; n4 < 4; n4++)
#pragma unroll
                    for (int ks = 0; ks < 4; ks++)
                        mma16816(&C[n4 * 4], &Ah[ks * 4], Breg[h * 4 + n4][ks]);

                uint32_t ka[8], kb[8];
#pragma unroll
                for (int n4 = 0; n4 < 4; n4++) {
#pragma unroll
                    for (int u = 0; u < 2; u++) {
                        int j = jw + h * 32 + n4 * 8 + 2 * (lane & 3) + u;
                        float hh = hreg[h * 8 + n4 * 2 + u];
                        ka[n4 * 2 + u] = mkkey(C[n4 * 4 + u] - hh, j);
                        kb[n4 * 2 + u] = mkkey(C[n4 * 4 + 2 + u] - hh, j);
                    }
                }
                uint32_t h1, h2;
                top2of8(ka, h1, h2);
                if (h == 0) { a1 = h1; a2 = h2; }
                else        pmerge(a1, a2, h1, h2);
                top2of8(kb, h1, h2);
                if (h == 0) { b1 = h1; b2 = h2; }
                else        pmerge(b1, b2, h1, h2);
            }
            // cross-lane top-2 over the 4 lanes sharing each row
#pragma unroll
            for (int m = 1; m <= 2; m <<= 1) {
                uint32_t o1 = __shfl_xor_sync(0xffffffffu, a1, m);
                uint32_t o2 = __shfl_xor_sync(0xffffffffu, a2, m);
                pmerge(a1, a2, o1, o2);
                o1 = __shfl_xor_sync(0xffffffffu, b1, m);
                o2 = __shfl_xor_sync(0xffffffffu, b2, m);
                pmerge(b1, b2, o1, o2);
            }
            if ((lane & 3) == 0) {
                int g = lane >> 2;
                sR2[(16 * rt + g) * 8 + wid]     = make_uint2(a1, a2);
                sR2[(16 * rt + g + 8) * 8 + wid] = make_uint2(b1, b2);
            }
        }
        __syncthreads();

        // ---- per-row combine: 2 threads/row (warps 0-3), then 1 shfl ----
        if (tid < 128) {
            int row = tid >> 1, half = tid & 1;
            uint2 v0 = sR2[row * 8 + half * 4];
            uint32_t m1 = v0.x, m2 = v0.y;
#pragma unroll
            for (int w = 1; w < 4; w++) {
                uint2 v = sR2[row * 8 + half * 4 + w];
                pmerge(m1, m2, v.x, v.y);
            }
            uint32_t o1 = __shfl_xor_sync(0xffffffffu, m1, 1);
            uint32_t o2 = __shfl_xor_sync(0xffffffffu, m2, 1);
            pmerge(m1, m2, o1, o2);
            if (half == 0) {
                float f1 = dkey(m1), f2 = dkey(m2);
                sBI[row] = 511 - (int)(m1 & 0x1FFu);
                sBest[row] = f1;
                int flag = (f1 - f2 < TAU) ? 1 : 0;
                sFlg[row] = (unsigned char)flag;
                if (flag) {
                    int p = atomicAdd(sNF, 1);
                    sLst[p] = row;
                }
            }
        }
        __syncthreads();
        const int nflag = *sNF;
        const bool mine_flagged = sFlg[myrow] != 0;

        // ---- epilogue helper (z from smem zoff) ----
        auto do_epilogue = [&](int bi) {
            size_t rg = (size_t)tile * TROWS + myrow;
            if (myq == 0) {
                out[O_IDX + rg] = (float)bi;
                atomicAdd(&sCnt[bi], 1.0f);
            }
            const float4* er = (const float4*)(emb + (size_t)bi * CD + myq * 16);
            const float4* zr = (const float4*)(smem + zoff + myrow * 256 + myq * 64);
            float4* oq = (float4*)(out + O_ZQ + rg * CD + myq * 16);
            float* es = g_esum + (size_t)bi * CD + myq * 16;
#pragma unroll
            for (int i = 0; i < 4; i++) {
                float4 e = er[i], zf = zr[i];
                float d0 = e.x - zf.x, d1 = e.y - zf.y;
                float d2 = e.z - zf.z, d3 = e.w - zf.w;
                sse_acc += d0 * d0 + d1 * d1 + d2 * d2 + d3 * d3;
                oq[i] = make_float4(zf.x + d0, zf.y + d1, zf.z + d2, zf.w + d3);
                asm volatile("red.global.add.v4.f32 [%0], {%1,%2,%3,%4};"
                    :: "l"(es + i * 4), "f"(zf.x), "f"(zf.y), "f"(zf.z), "f"(zf.w)
                    : "memory");
            }
        };

        // ---- epilogue for unflagged rows (overlaps recheck below) ----
        if (!mine_flagged) do_epilogue(sBI[myrow]);

        // ---- candidate-pruned exact recheck for flagged rows ----
        if (nflag > 0) {
#pragma unroll 1
            for (int li = wid; li < nflag; li += 8) {
                int rowl = sLst[li];
                float thr = sBest[rowl] - TAU;
                float wb = -3.4e38f, wb2 = -3.4e38f; int wic = 0;
                if (lane < 8) {
                    uint2 v = sR2[rowl * 8 + lane];
                    wb = dkey(v.x); wb2 = dkey(v.y);
                    wic = 511 - (int)(v.x & 0x1FFu);
                }
                unsigned candm  = __ballot_sync(0xffffffffu, wb  >= thr);
                unsigned heavym = __ballot_sync(0xffffffffu, wb  >= thr && wb2 >= thr);
                unsigned lightm = candm & ~heavym;

                float4 f[16];
                {
                    const float4* zr = (const float4*)(smem + zoff + rowl * 256);
#pragma unroll
                    for (int i = 0; i < 16; i++) f[i] = zr[i];
                }
                float lb = -3.4e38f; int lj = NC;
                if (lightm & (1u << lane)) {
                    lb = exact_score(f, emb, sH, wic);
                    lj = wic;
                }
#pragma unroll 1
                while (heavym) {       // heavy block = 64 codes -> 2 scans
                    int c = __ffs(heavym) - 1; heavym &= heavym - 1;
#pragma unroll
                    for (int s = 0; s < 2; s++) {
                        int j = 64 * c + 32 * s + lane;
                        float sc = exact_score(f, emb, sH, j);
                        if (sc > lb || (sc == lb && j < lj)) { lb = sc; lj = j; }
                    }
                }
#pragma unroll
                for (int m = 16; m; m >>= 1) {
                    float ob = __shfl_xor_sync(0xffffffffu, lb, m);
                    int   oj = __shfl_xor_sync(0xffffffffu, lj, m);
                    if (ob > lb || (ob == lb && oj < lj)) { lb = ob; lj = oj; }
                }
                if (lane == 0) sBI[rowl] = lj;
            }
            __syncthreads();
            // ---- deferred epilogue for flagged rows ----
            if (mine_flagged) do_epilogue(sBI[myrow]);
        }
    }

    // ---- final merges ----
    __syncthreads();
#pragma unroll
    for (int i = 0; i < 2; i++) {
        float c = sCnt[tid + 256 * i];
        if (c != 0.0f) atomicAdd(&g_counts[tid + 256 * i], c);
    }
#pragma unroll
    for (int m = 16; m; m >>= 1) sse_acc += __shfl_xor_sync(0xffffffffu, sse_acc, m);
    if (lane == 0 && sse_acc != 0.0f) atomicAdd(&g_sse, sse_acc);
}

// ============================================================================
// Kernel 3: finalize EMA + loss. 64 blocks x 512 thr.
// ============================================================================
__global__ void vq_final(const float* __restrict__ cluster_size,
                         const float* __restrict__ embedding_avg,
                         float* __restrict__ out) {
    __shared__ float sncs[NC];
    __shared__ float sred[NC];
    const int t = threadIdx.x;
    const int b = blockIdx.x;

    float ncs = cluster_size[t] * 0.99f + 0.01f * g_counts[t];
    sncs[t] = ncs;
    sred[t] = ncs;
    if (b == 0) out[O_NCS + t] = ncs;
    __syncthreads();
#pragma unroll
    for (int o = NC / 2; o > 0; o >>= 1) {
        if (t < o) sred[t] += sred[t + o];
        __syncthreads();
    }
    const float n = sred[0];

    const int code = 8 * b + (t >> 6);
    const int k = t & 63;
    const size_t o = (size_t)code * CD + k;
    float ea = embedding_avg[o] * 0.99f + 0.01f * g_esum[o];
    out[O_NAVG + o] = ea;
    float cs = (sncs[code] + 1e-6f) / (n + (float)NC * 1e-6f);
    out[O_NEMB + o] = ea / cs;

    if (b == 0 && t == 0) out[O_LOSS] = 0.25f * g_sse / (float)NELEM;
}

// ============================================================================
extern "C" void kernel_launch(void* const* d_in, const int* in_sizes, int n_in,
                              void* d_out, int out_size) {
    const float* z    = (const float*)d_in[0];
    const float* emb  = (const float*)d_in[1];
    const float* csz  = (const float*)d_in[2];
    const float* eavg = (const float*)d_in[3];
    float* out = (float*)d_out;

    cudaFuncSetAttribute(vq_main, cudaFuncAttributeMaxDynamicSharedMemorySize, SMEM_SZ);
    vq_init<<<64, 512>>>(emb);
    vq_nop1<<<1, 1>>>();
    vq_nop2<<<1, 1>>>();
    vq_main<<<GRID, 256, SMEM_SZ>>>(z, emb, out);
    vq_final<<<64, NC>>>(csz, eavg, out);
}